// round 8
// baseline (speedup 1.0000x reference)
#include <cuda_runtime.h>
#include <cuda_fp16.h>
#include <math.h>
#include <stdint.h>

// ---------------------------------------------------------------------------
// Problem constants
//   B=4, SEQ=1024, DIM=1024, HEADS=16, HD=64, N_EXP=2, SLOTS=512, HID=4096
// Output: [ y : 4*1024*1024 f32 ][ attn : 4*1024*1024*16 f32 ]
// ---------------------------------------------------------------------------

#define OFF_Q       0LL
#define OFF_KV      4194304LL
#define OFF_TMP     12582912LL     // attn E=exp(S) scratch, fp16 (b,h,n,m) 64M halves
#define OFF_ATTOUT  79691776LL
#define OFF_PROJ    83886080LL
#define OFF_X1      88080384LL
#define OFF_LOGITS  92274688LL
#define OFF_DISPT   96468992LL
#define OFF_COMB    100663296LL
#define OFF_SLOTS   104857600LL
#define OFF_H       109051904LL    // 16M floats
#define OFF_YMOE    125829120LL
#define OFF_MOE     130023424LL
#define OFF_RL      134283264LL
// tf32-rounded copies of harness inputs
#define OFF_XR      134348800LL
#define OFF_WQR     138543104LL
#define OFF_WKVR    139591680LL
#define OFF_WPR     141688832LL
#define OFF_PHIR    142737408LL
#define OFF_WE1R    143785984LL
#define OFF_WE2R    152174592LL
#define ARENA_FLOATS 160563200LL

__device__ float g_arena[ARENA_FLOATS];

__device__ __forceinline__ float gelu_tanh(float v) {
    const float c0 = 0.7978845608028654f;   // sqrt(2/pi)
    float t = tanhf(c0 * (v + 0.044715f * v * v * v));
    return 0.5f * v * (1.0f + t);
}

__device__ __forceinline__ float to_tf32(float x) {
    float r;
    asm("cvt.rna.tf32.f32 %0, %1;" : "=f"(r) : "f"(x));
    return r;
}

__device__ __forceinline__ uint32_t smem_u32(const void* p) {
    return (uint32_t)__cvta_generic_to_shared(p);
}

#define CP16(dst, src) \
    asm volatile("cp.async.cg.shared.global [%0], [%1], 16;" :: "r"(dst), "l"(src))
#define CP_COMMIT() asm volatile("cp.async.commit_group;")
#define CP_WAIT0()  asm volatile("cp.async.wait_group 0;")

#define MMA_TF32(c0,c1,c2,c3,a0,a1,a2,a3,b0,b1)                               \
    asm volatile("mma.sync.aligned.m16n8k8.row.col.f32.tf32.tf32.f32 "        \
                 "{%0,%1,%2,%3},{%4,%5,%6,%7},{%8,%9},{%0,%1,%2,%3};"         \
                 : "+f"(c0), "+f"(c1), "+f"(c2), "+f"(c3)                     \
                 : "r"(a0), "r"(a1), "r"(a2), "r"(a3), "r"(b0), "r"(b1))

#define LDSM_X4(r0,r1,r2,r3,addr)                                             \
    asm volatile("ldmatrix.sync.aligned.m8n8.x4.shared.b16 {%0,%1,%2,%3}, [%4];" \
                 : "=r"(r0), "=r"(r1), "=r"(r2), "=r"(r3) : "r"(addr))

extern __shared__ float dynsm[];

// ---------------------------------------------------------------------------
// RNA-round a buffer to tf32 (element count multiple of 4).
// ---------------------------------------------------------------------------
__global__ void round_buf(const float* __restrict__ src, float* __restrict__ dst, int n4)
{
    int i = blockIdx.x * blockDim.x + threadIdx.x;
    if (i < n4) {
        float4 v = ((const float4*)src)[i];
        v.x = to_tf32(v.x); v.y = to_tf32(v.y);
        v.z = to_tf32(v.z); v.w = to_tf32(v.w);
        ((float4*)dst)[i] = v;
    }
}

// ---------------------------------------------------------------------------
// tf32 tensor-core batched GEMM. cp.async double-buffer, k-chunk 32,
// ldmatrix A-fragments. Inputs must be tf32-representable (rounded at
// producer); HW truncation lossless.
// C = A(MxK) @ B(KxN) [+bias] [gelu] [round-out]. M,N mult 128, K mult 32.
// 8 warps (2x4), warp tile 64x32, m16n8k8. Dynamic smem 71.7KB.
// Layout: As[2][128][36] ([m][k32 pad 36]), Bs[2][32][136] ([k][n128 pad 136])
// ---------------------------------------------------------------------------
__global__ void __launch_bounds__(256, 2)
tgemm(const float* __restrict__ A, const float* __restrict__ Bm,
      const float* __restrict__ bias, float* __restrict__ C,
      int M, int N, int K,
      long long sA, long long sB, long long sBias, long long sC,
      int nBmod, int act, int rOut)
{
    int z = blockIdx.z;
    int zb = nBmod ? (z % nBmod) : z;
    A  += (long long)z * sA;
    Bm += (long long)zb * sB;
    if (act >= 1) bias += (long long)zb * sBias;
    C  += (long long)z * sC;

    float* As = dynsm;           // [2][128][36]
    float* Bs = dynsm + 9216;    // [2][32][136]

    int bx = blockIdx.x, by = blockIdx.y;
    int tid = threadIdx.x;
    int wid = tid >> 5;
    int lane = tid & 31;
    int g = lane >> 2;
    int j = lane & 3;
    int wm64 = (wid >> 2) * 64;
    int wn32 = (wid & 3) * 32;

    // gmem->smem load mapping (4 CP16 each for A and B per k32)
    int aRow = tid >> 1;             // 0..127
    int aKc  = (tid & 1) * 16;       // 0 or 16
    int bRow = tid >> 3;             // 0..31
    int bCc  = (tid & 7) * 16;       // 0..112

    const float* Ap = A + (long long)(by * 128 + aRow) * K + aKc;
    const float* Bp = Bm + (long long)bRow * N + bx * 128 + bCc;

    uint32_t aSm = smem_u32(&As[aRow * 36 + aKc]);
    uint32_t bSm = smem_u32(&Bs[bRow * 136 + bCc]);

    // ldmatrix A-fragment addresses: lane l -> matrix l>>3, row l&7.
    // mat&1 selects +8 m-rows, mat>>1 selects +4 k-cols.
    int mat = lane >> 3;
    int mrow = lane & 7;
    uint32_t aFrag[4];
    #pragma unroll
    for (int mt = 0; mt < 4; mt++)
        aFrag[mt] = smem_u32(
            &As[(wm64 + mt * 16 + (mat & 1) * 8 + mrow) * 36 + (mat >> 1) * 4]);

    float c[4][4][4];
    #pragma unroll
    for (int mt = 0; mt < 4; mt++)
        #pragma unroll
        for (int nt = 0; nt < 4; nt++)
            #pragma unroll
            for (int r = 0; r < 4; r++) c[mt][nt][r] = 0.0f;

    // issue tile 0
    #pragma unroll
    for (int i = 0; i < 4; i++) {
        CP16(aSm + i * 16, Ap + i * 4);
        CP16(bSm + i * 16, Bp + i * 4);
    }
    CP_COMMIT();

    int buf = 0;
    for (int k0 = 0; k0 < K; k0 += 32) {
        CP_WAIT0();
        __syncthreads();   // tile visible block-wide; prior compute on buf^1 done

        if (k0 + 32 < K) {
            Ap += 32;
            Bp += (long long)32 * N;
            uint32_t aD = aSm + (buf ^ 1) * 18432;   // 4608 floats
            uint32_t bD = bSm + (buf ^ 1) * 17408;   // 4352 floats
            #pragma unroll
            for (int i = 0; i < 4; i++) {
                CP16(aD + i * 16, Ap + i * 4);
                CP16(bD + i * 16, Bp + i * 4);
            }
            CP_COMMIT();
        }

        uint32_t bufA = (uint32_t)buf * 18432;       // bytes
        const float* Bbuf = Bs + buf * 4352;

        #pragma unroll
        for (int kk = 0; kk < 32; kk += 8) {
            uint32_t a[4][4];
            uint32_t bfr[4][2];
            #pragma unroll
            for (int mt = 0; mt < 4; mt++)
                LDSM_X4(a[mt][0], a[mt][1], a[mt][2], a[mt][3],
                        aFrag[mt] + bufA + kk * 4);
            const float* pB = Bbuf + (kk + j) * 136 + wn32 + g;
            #pragma unroll
            for (int nt = 0; nt < 4; nt++) {
                bfr[nt][0] = __float_as_uint(pB[nt * 8]);
                bfr[nt][1] = __float_as_uint(pB[nt * 8 + 544]);   // +4 k-rows
            }
            #pragma unroll
            for (int mt = 0; mt < 4; mt++)
                #pragma unroll
                for (int nt = 0; nt < 4; nt++)
                    MMA_TF32(c[mt][nt][0], c[mt][nt][1], c[mt][nt][2], c[mt][nt][3],
                             a[mt][0], a[mt][1], a[mt][2], a[mt][3],
                             bfr[nt][0], bfr[nt][1]);
        }
        buf ^= 1;
    }

    // epilogue
    #pragma unroll
    for (int mt = 0; mt < 4; mt++) {
        int r0 = by * 128 + wm64 + mt * 16 + g;
        #pragma unroll
        for (int nt = 0; nt < 4; nt++) {
            int col = bx * 128 + wn32 + nt * 8 + 2 * j;
            float b0 = 0.0f, b1 = 0.0f;
            if (act >= 1) { b0 = bias[col]; b1 = bias[col + 1]; }
            float v0 = c[mt][nt][0] + b0;
            float v1 = c[mt][nt][1] + b1;
            float v2 = c[mt][nt][2] + b0;
            float v3 = c[mt][nt][3] + b1;
            if (act == 2) {
                v0 = gelu_tanh(v0); v1 = gelu_tanh(v1);
                v2 = gelu_tanh(v2); v3 = gelu_tanh(v3);
            }
            if (rOut) {
                v0 = to_tf32(v0); v1 = to_tf32(v1);
                v2 = to_tf32(v2); v3 = to_tf32(v3);
            }
            *(float2*)(C + (long long)r0 * N + col)       = make_float2(v0, v1);
            *(float2*)(C + (long long)(r0 + 8) * N + col) = make_float2(v2, v3);
        }
    }
}

// ---------------------------------------------------------------------------
// Fused attention (tensor cores): per (b,h), n-tile 64.
// S = Q K^T (q/kv pre-rounded tf32); E = exp(0.125*S) -> tmp fp16 streaming;
// P = tf32(E) -> smem; O = (P@V)/Σ, rounded tf32 (feeds proj GEMM).
// Dynamic smem: Qs(64x68) Kt(64x68) Vs(64x72) Ps(64x68) sums(4x64) = 71.7KB
// ---------------------------------------------------------------------------
__global__ void __launch_bounds__(256)
att_fused(const float* __restrict__ q, const float* __restrict__ kv,
          __half* __restrict__ tmp, float* __restrict__ rowrl,
          float* __restrict__ attout)
{
    int bh = blockIdx.y;
    int b = bh >> 4, h = bh & 15;
    int n0 = blockIdx.x * 64;

    float* Qs   = dynsm;            // [n][d] pad 68
    float* Kt   = dynsm + 4352;     // [m][d] pad 68
    float* Vs   = dynsm + 8704;     // [m][d] pad 72
    float* Ps   = dynsm + 13312;    // [n][m] pad 68
    float* sums = dynsm + 17664;    // [4][64]

    int tid = threadIdx.x, lane = tid & 31, wid = tid >> 5;
    int g = lane >> 2, j = lane & 3;
    int wm32 = (wid >> 2) * 32;
    int wn16 = (wid & 3) * 16;

    sums[tid & 255] = 0.0f;

    for (int i = tid; i < 1024; i += 256) {
        int r = i >> 4, c4 = (i & 15) * 4;
        *(float4*)&Qs[r * 68 + c4] =
            *(const float4*)(q + ((size_t)(b * 1024 + n0 + r) * 1024) + h * 64 + c4);
    }

    float o[2][2][4];
    #pragma unroll
    for (int mt = 0; mt < 2; mt++)
        #pragma unroll
        for (int nt = 0; nt < 2; nt++)
            #pragma unroll
            for (int r = 0; r < 4; r++) o[mt][nt][r] = 0.0f;

    for (int m0 = 0; m0 < 1024; m0 += 64) {
        __syncthreads();
        for (int i = tid; i < 1024; i += 256) {
            int r = i >> 4, c4 = (i & 15) * 4;
            const float* kb = kv + ((size_t)(b * 1024 + m0 + r) * 2048) + h * 64 + c4;
            *(float4*)&Kt[r * 68 + c4] = *(const float4*)kb;
            *(float4*)&Vs[r * 72 + c4] = *(const float4*)(kb + 1024);
        }
        __syncthreads();

        // S-mma (operands already tf32-representable; truncation lossless)
        float c[2][2][4];
        #pragma unroll
        for (int mt = 0; mt < 2; mt++)
            #pragma unroll
            for (int nt = 0; nt < 2; nt++)
                #pragma unroll
                for (int r = 0; r < 4; r++) c[mt][nt][r] = 0.0f;

        #pragma unroll
        for (int kk = 0; kk < 64; kk += 8) {
            uint32_t a[2][4], bf[2][2];
            #pragma unroll
            for (int mt = 0; mt < 2; mt++) {
                const float* p = &Qs[(wm32 + mt * 16 + g) * 68 + kk + j];
                a[mt][0] = __float_as_uint(p[0]);
                a[mt][1] = __float_as_uint(p[8 * 68]);
                a[mt][2] = __float_as_uint(p[4]);
                a[mt][3] = __float_as_uint(p[8 * 68 + 4]);
            }
            #pragma unroll
            for (int nt = 0; nt < 2; nt++) {
                const float* p = &Kt[(wn16 + nt * 8 + g) * 68 + kk + j];
                bf[nt][0] = __float_as_uint(p[0]);
                bf[nt][1] = __float_as_uint(p[4]);
            }
            #pragma unroll
            for (int mt = 0; mt < 2; mt++)
                #pragma unroll
                for (int nt = 0; nt < 2; nt++)
                    MMA_TF32(c[mt][nt][0], c[mt][nt][1], c[mt][nt][2], c[mt][nt][3],
                             a[mt][0], a[mt][1], a[mt][2], a[mt][3],
                             bf[nt][0], bf[nt][1]);
        }

        // E = exp(0.125*S): tmp fp16 (streaming), Ps = tf32(E), row sums
        #pragma unroll
        for (int mt = 0; mt < 2; mt++) {
            int r1 = wm32 + mt * 16 + g;
            float eA = 0.0f, eB = 0.0f;
            #pragma unroll
            for (int nt = 0; nt < 2; nt++) {
                int col = wn16 + nt * 8 + 2 * j;
                float e0 = to_tf32(__expf(0.125f * c[mt][nt][0]));
                float e1 = to_tf32(__expf(0.125f * c[mt][nt][1]));
                float e2 = to_tf32(__expf(0.125f * c[mt][nt][2]));
                float e3 = to_tf32(__expf(0.125f * c[mt][nt][3]));
                size_t idx = ((size_t)bh * 1024 + n0 + r1) * 1024 + m0 + col;
                __half2 h01 = __floats2half2_rn(e0, e1);
                __half2 h23 = __floats2half2_rn(e2, e3);
                __stcs((unsigned int*)(tmp + idx),            *(unsigned int*)&h01);
                __stcs((unsigned int*)(tmp + idx + 8 * 1024), *(unsigned int*)&h23);
                *(float2*)&Ps[r1 * 68 + col]       = make_float2(e0, e1);
                *(float2*)&Ps[(r1 + 8) * 68 + col] = make_float2(e2, e3);
                eA += e0 + e1;
                eB += e2 + e3;
            }
            eA += __shfl_xor_sync(0xffffffffu, eA, 1);
            eA += __shfl_xor_sync(0xffffffffu, eA, 2);
            eB += __shfl_xor_sync(0xffffffffu, eB, 1);
            eB += __shfl_xor_sync(0xffffffffu, eB, 2);
            if (j == 0) {
                sums[(wn16 >> 4) * 64 + r1]     += eA;
                sums[(wn16 >> 4) * 64 + r1 + 8] += eB;
            }
        }
        __syncthreads();

        // PV-mma: A = Ps (tf32 E), B = Vs (tf32 V)
        #pragma unroll
        for (int kk = 0; kk < 64; kk += 8) {
            uint32_t a[2][4], bf[2][2];
            #pragma unroll
            for (int mt = 0; mt < 2; mt++) {
                const float* p = &Ps[(wm32 + mt * 16 + g) * 68 + kk + j];
                a[mt][0] = __float_as_uint(p[0]);
                a[mt][1] = __float_as_uint(p[8 * 68]);
                a[mt][2] = __float_as_uint(p[4]);
                a[mt][3] = __float_as_uint(p[8 * 68 + 4]);
            }
            #pragma unroll
            for (int nt = 0; nt < 2; nt++) {
                const float* p = &Vs[(kk + j) * 72 + wn16 + nt * 8 + g];
                bf[nt][0] = __float_as_uint(p[0]);
                bf[nt][1] = __float_as_uint(p[4 * 72]);
            }
            #pragma unroll
            for (int mt = 0; mt < 2; mt++)
                #pragma unroll
                for (int nt = 0; nt < 2; nt++)
                    MMA_TF32(o[mt][nt][0], o[mt][nt][1], o[mt][nt][2], o[mt][nt][3],
                             a[mt][0], a[mt][1], a[mt][2], a[mt][3],
                             bf[nt][0], bf[nt][1]);
        }
    }

    __syncthreads();
    if (tid < 64) {
        float tot = sums[tid] + sums[64 + tid] + sums[128 + tid] + sums[192 + tid];
        float r = 1.0f / tot;
        sums[tid] = r;                                 // reuse as reciprocal
        rowrl[(size_t)bh * 1024 + n0 + tid] = r;
    }
    __syncthreads();

    #pragma unroll
    for (int mt = 0; mt < 2; mt++) {
        int r1 = wm32 + mt * 16 + g;
        float rlA = sums[r1], rlB = sums[r1 + 8];
        #pragma unroll
        for (int nt = 0; nt < 2; nt++) {
            int col = wn16 + nt * 8 + 2 * j;
            float* base = attout + ((size_t)(b * 1024 + n0 + r1) * 1024) + h * 64 + col;
            *(float2*)base = make_float2(to_tf32(o[mt][nt][0] * rlA),
                                         to_tf32(o[mt][nt][1] * rlA));
            *(float2*)(base + 8 * 1024) = make_float2(to_tf32(o[mt][nt][2] * rlB),
                                                      to_tf32(o[mt][nt][3] * rlB));
        }
    }
}

// ---------------------------------------------------------------------------
// Normalize + transpose: out(b,n,m,h) = E_fp16(b,h,n,m) * rl(b,h,n).
// Block per (b,n); loops 4 m-chunks of 256. Streaming hints.
// ---------------------------------------------------------------------------
__global__ void attn_tr(const __half* __restrict__ tmp, const float* __restrict__ rowrl,
                        float* __restrict__ outAttn)
{
    int b = blockIdx.y;
    int n = blockIdx.x;
    __shared__ float T[16][257];
    __shared__ float rl_s[16];
    int tid = threadIdx.x;
    if (tid < 16) rl_s[tid] = rowrl[(size_t)(b * 16 + tid) * 1024 + n];
    __syncthreads();

    for (int m0 = 0; m0 < 1024; m0 += 256) {
        for (int i = tid; i < 16 * 128; i += 256) {
            int hh = i >> 7, mm = (i & 127) * 2;
            unsigned int raw = __ldcs((const unsigned int*)
                (tmp + ((size_t)(b * 16 + hh) * 1024 + n) * 1024 + m0 + mm));
            __half2 v = *(__half2*)&raw;
            float2 f = __half22float2(v);
            float rl = rl_s[hh];
            T[hh][mm]     = f.x * rl;
            T[hh][mm + 1] = f.y * rl;
        }
        __syncthreads();
        float* dst = outAttn + ((size_t)(b * 1024 + n) * 1024 + m0 + tid) * 16;
        #pragma unroll
        for (int k = 0; k < 16; k += 4) {
            __stcs((float4*)(dst + k),
                   make_float4(T[k][tid], T[k + 1][tid], T[k + 2][tid], T[k + 3][tid]));
        }
        __syncthreads();
    }
}

// ---------------------------------------------------------------------------
// Row softmax over contiguous 1024 (combine weights), tf32-rounded out.
// ---------------------------------------------------------------------------
__global__ void row_softmax(const float* __restrict__ in, float* __restrict__ outp)
{
    size_t row = blockIdx.x;
    const float4* L = (const float4*)(in + row * 1024);
    float4* O = (float4*)(outp + row * 1024);
    int t = threadIdx.x;
    float4 v = L[t];
    float mx = fmaxf(fmaxf(v.x, v.y), fmaxf(v.z, v.w));
    __shared__ float smA[8], smB[8];
    #pragma unroll
    for (int off = 16; off; off >>= 1) mx = fmaxf(mx, __shfl_xor_sync(0xffffffffu, mx, off));
    if ((t & 31) == 0) smA[t >> 5] = mx;
    __syncthreads();
    mx = smA[0];
    #pragma unroll
    for (int w = 1; w < 8; w++) mx = fmaxf(mx, smA[w]);
    float e0 = __expf(v.x - mx), e1 = __expf(v.y - mx);
    float e2 = __expf(v.z - mx), e3 = __expf(v.w - mx);
    float s = e0 + e1 + e2 + e3;
    #pragma unroll
    for (int off = 16; off; off >>= 1) s += __shfl_xor_sync(0xffffffffu, s, off);
    if ((t & 31) == 0) smB[t >> 5] = s;
    __syncthreads();
    s = 0.0f;
    #pragma unroll
    for (int w = 0; w < 8; w++) s += smB[w];
    float r = 1.0f / s;
    O[t] = make_float4(to_tf32(e0 * r), to_tf32(e1 * r), to_tf32(e2 * r), to_tf32(e3 * r));
}

// ---------------------------------------------------------------------------
// Dispatch softmax over token axis n, written TRANSPOSED + tf32-rounded.
// ---------------------------------------------------------------------------
__global__ void disp_softmax(const float* __restrict__ logits, float* __restrict__ dispT)
{
    int b = blockIdx.y;
    int c0 = blockIdx.x * 64;
    const float* L = logits + (size_t)b * 1048576;
    float* O = dispT + (size_t)b * 1048576;
    int tid = threadIdx.x;
    int tx = tid & 63, ty = tid >> 6;   // 4 x 64
    int col = c0 + tx;

    __shared__ float red[4][64];
    float mx = -1e30f;
    for (int n = ty; n < 1024; n += 4) mx = fmaxf(mx, L[(size_t)n * 1024 + col]);
    red[ty][tx] = mx;
    __syncthreads();
    mx = fmaxf(fmaxf(red[0][tx], red[1][tx]), fmaxf(red[2][tx], red[3][tx]));
    __syncthreads();
    float s = 0.0f;
    for (int n = ty; n < 1024; n += 4) s += __expf(L[(size_t)n * 1024 + col] - mx);
    red[ty][tx] = s;
    __syncthreads();
    s = red[0][tx] + red[1][tx] + red[2][tx] + red[3][tx];
    float rinv = 1.0f / s;
    __syncthreads();

    __shared__ float T[64][65];
    for (int n0 = 0; n0 < 1024; n0 += 64) {
        for (int n = ty; n < 64; n += 4)
            T[tx][n] = to_tf32(__expf(L[(size_t)(n0 + n) * 1024 + col] - mx) * rinv);
        __syncthreads();
        int cl = tid >> 2;
        int nl = (tid & 3) * 16;
        float* dst = O + (size_t)(c0 + cl) * 1024 + n0 + nl;
        #pragma unroll
        for (int k = 0; k < 16; k += 4)
            *(float4*)(dst + k) = make_float4(T[cl][nl + k], T[cl][nl + k + 1],
                                              T[cl][nl + k + 2], T[cl][nl + k + 3]);
        __syncthreads();
    }
}

// ---------------------------------------------------------------------------
// Fused residual + LayerNorm: out = LN(a + coefb * bsrc) * g + beta [round]
// ---------------------------------------------------------------------------
__global__ void ln_res(const float* __restrict__ a, const float* __restrict__ bsrc,
                       float coefb, const float* __restrict__ g,
                       const float* __restrict__ beta, float* __restrict__ outp,
                       int rOut)
{
    size_t row = blockIdx.x;
    int t = threadIdx.x;
    float4 av = ((const float4*)(a + row * 1024))[t];
    float4 bv = ((const float4*)(bsrc + row * 1024))[t];
    float x0 = av.x + coefb * bv.x;
    float x1 = av.y + coefb * bv.y;
    float x2 = av.z + coefb * bv.z;
    float x3 = av.w + coefb * bv.w;
    float s = x0 + x1 + x2 + x3;
    float q = x0 * x0 + x1 * x1 + x2 * x2 + x3 * x3;
    __shared__ float smA[8], smB[8];
    #pragma unroll
    for (int off = 16; off; off >>= 1) {
        s += __shfl_xor_sync(0xffffffffu, s, off);
        q += __shfl_xor_sync(0xffffffffu, q, off);
    }
    if ((t & 31) == 0) { smA[t >> 5] = s; smB[t >> 5] = q; }
    __syncthreads();
    s = 0.0f; q = 0.0f;
    #pragma unroll
    for (int w = 0; w < 8; w++) { s += smA[w]; q += smB[w]; }
    float mu = s * (1.0f / 1024.0f);
    float var = q * (1.0f / 1024.0f) - mu * mu;
    float rs = rsqrtf(var + 1e-5f);
    float4 gv = ((const float4*)g)[t];
    float4 btv = ((const float4*)beta)[t];
    float4 out4;
    out4.x = (x0 - mu) * rs * gv.x + btv.x;
    out4.y = (x1 - mu) * rs * gv.y + btv.y;
    out4.z = (x2 - mu) * rs * gv.z + btv.z;
    out4.w = (x3 - mu) * rs * gv.w + btv.w;
    if (rOut) {
        out4.x = to_tf32(out4.x); out4.y = to_tf32(out4.y);
        out4.z = to_tf32(out4.z); out4.w = to_tf32(out4.w);
    }
    ((float4*)(outp + row * 1024))[t] = out4;
}

// ---------------------------------------------------------------------------
// Launcher
// ---------------------------------------------------------------------------
extern "C" void kernel_launch(void* const* d_in, const int* in_sizes, int n_in,
                              void* d_out, int out_size)
{
    const float* x   = (const float*)d_in[0];
    const float* Wq  = (const float*)d_in[1];
    const float* bq  = (const float*)d_in[2];
    const float* Wkv = (const float*)d_in[3];
    const float* bkv = (const float*)d_in[4];
    const float* Wp  = (const float*)d_in[5];
    const float* bp  = (const float*)d_in[6];
    const float* g1  = (const float*)d_in[7];
    const float* b1  = (const float*)d_in[8];
    const float* phi = (const float*)d_in[9];
    const float* We1 = (const float*)d_in[10];
    const float* be1 = (const float*)d_in[11];
    const float* We2 = (const float*)d_in[12];
    const float* be2 = (const float*)d_in[13];
    const float* g2  = (const float*)d_in[14];
    const float* b2  = (const float*)d_in[15];

    float* arena = nullptr;
    cudaGetSymbolAddress((void**)&arena, g_arena);

    float* q      = arena + OFF_Q;
    float* kvb    = arena + OFF_KV;
    __half* tmp   = (__half*)(arena + OFF_TMP);
    float* attout = arena + OFF_ATTOUT;
    float* proj   = arena + OFF_PROJ;
    float* x1     = arena + OFF_X1;
    float* logits = arena + OFF_LOGITS;
    float* dispT  = arena + OFF_DISPT;
    float* comb   = arena + OFF_COMB;
    float* slots  = arena + OFF_SLOTS;
    float* hbuf   = arena + OFF_H;
    float* ymoe   = arena + OFF_YMOE;
    float* moeout = arena + OFF_MOE;
    float* rl     = arena + OFF_RL;
    float* xr     = arena + OFF_XR;
    float* WqR    = arena + OFF_WQR;
    float* WkvR   = arena + OFF_WKVR;
    float* WpR    = arena + OFF_WPR;
    float* phiR   = arena + OFF_PHIR;
    float* We1R   = arena + OFF_WE1R;
    float* We2R   = arena + OFF_WE2R;

    float* out = (float*)d_out;
    float* outAttn = out + 4194304;

    const int GEMM_SMEM = 71680;  // (2*4608 + 2*4352) floats
    const int ATT_SMEM  = 71680;  // Qs+Kt+Vs+Ps+sums
    cudaFuncSetAttribute(tgemm, cudaFuncAttributeMaxDynamicSharedMemorySize, GEMM_SMEM);
    cudaFuncSetAttribute(att_fused, cudaFuncAttributeMaxDynamicSharedMemorySize, ATT_SMEM);

    dim3 T(256);

    // prep: tf32-round harness inputs that feed GEMMs
    round_buf<<<4096, T>>>(x,   xr,   1048576);
    round_buf<<<1024, T>>>(Wq,  WqR,   262144);
    round_buf<<<2048, T>>>(Wkv, WkvR,  524288);
    round_buf<<<1024, T>>>(Wp,  WpR,   262144);
    round_buf<<<1024, T>>>(phi, phiR,  262144);
    round_buf<<<8192, T>>>(We1, We1R, 2097152);
    round_buf<<<8192, T>>>(We2, We2R, 2097152);

    // q = x @ Wq + bq          (4096x1024x1024) -> rounded
    tgemm<<<dim3(8, 32, 1), T, GEMM_SMEM>>>(xr, WqR, bq, q, 4096, 1024, 1024,
                                            0, 0, 0, 0, 1, 1, 1);
    // kv = x @ Wkv + bkv       (4096x2048x1024) -> rounded
    tgemm<<<dim3(16, 32, 1), T, GEMM_SMEM>>>(xr, WkvR, bkv, kvb, 4096, 2048, 1024,
                                             0, 0, 0, 0, 1, 1, 1);

    // fused attention + transpose
    att_fused<<<dim3(16, 64), T, ATT_SMEM>>>(q, kvb, tmp, rl, attout);
    attn_tr<<<dim3(1024, 4), T>>>(tmp, rl, outAttn);

    // out-proj + residual LN (x1 rounded: feeds logits/slots GEMMs)
    tgemm<<<dim3(8, 32, 1), T, GEMM_SMEM>>>(attout, WpR, bp, proj, 4096, 1024, 1024,
                                            0, 0, 0, 0, 1, 1, 0);
    ln_res<<<4096, T>>>(proj, x, 1.0f, g1, b1, x1, 1);

    // soft-MoE
    tgemm<<<dim3(8, 32, 1), T, GEMM_SMEM>>>(x1, phiR, nullptr, logits, 4096, 1024, 1024,
                                            0, 0, 0, 0, 1, 0, 0);
    row_softmax<<<4096, T>>>(logits, comb);
    disp_softmax<<<dim3(16, 4), T>>>(logits, dispT);

    // slots[b] = dispT[b] @ x1[b] -> rounded
    tgemm<<<dim3(8, 8, 4), T, GEMM_SMEM>>>(dispT, x1, nullptr, slots, 1024, 1024, 1024,
                                           1048576, 1048576, 0, 1048576, 0, 0, 1);
    // h = gelu(slots @ We1[e] + be1[e]) -> rounded
    tgemm<<<dim3(32, 4, 8), T, GEMM_SMEM>>>(slots, We1R, be1, hbuf, 512, 4096, 1024,
                                            524288, 4194304, 4096, 2097152, 2, 2, 1);
    // y = h @ We2[e] + be2[e] -> rounded
    tgemm<<<dim3(8, 4, 8), T, GEMM_SMEM>>>(hbuf, We2R, be2, ymoe, 512, 1024, 4096,
                                           2097152, 4194304, 1024, 524288, 2, 1, 1);
    // moe_out[b] = comb[b] @ ymoe[b]
    tgemm<<<dim3(8, 8, 4), T, GEMM_SMEM>>>(comb, ymoe, nullptr, moeout, 1024, 1024, 1024,
                                           1048576, 1048576, 0, 1048576, 0, 0, 0);

    // y = LN(moe_out + 2*x1)
    ln_res<<<4096, T>>>(moeout, x1, 2.0f, g2, b2, out, 0);
}

// round 11
// speedup vs baseline: 1.9038x; 1.9038x over previous
#include <cuda_runtime.h>
#include <cuda_fp16.h>
#include <math.h>
#include <stdint.h>

// ---------------------------------------------------------------------------
// Problem constants
//   B=4, SEQ=1024, DIM=1024, HEADS=16, SEQ=1024, N_EXP=2, SLOTS=512, HID=4096
// Output: [ y : 4*1024*1024 f32 ][ attn : 4*1024*1024*16 f32 ]
// All GEMM/attention operands fp16 (RNE-rounded at producer), fp32 accumulate.
// ---------------------------------------------------------------------------

// arena offsets in FLOAT units (fp16 buffers occupy elem_count/2 float slots)
#define OFF_TMP      0LL           // 64M halves = 32M floats
#define OFF_PROJ     33554432LL    // 4M f32
#define OFF_X1       37748736LL    // 4M f32
#define OFF_LOGITS   41943040LL    // 4M f32
#define OFF_MOE      46137344LL    // 4M f32
#define OFF_RL       50331648LL    // 64K f32
#define OFF_XH       50397184LL    // 4M halves
#define OFF_WQH      52494336LL    // 1M halves
#define OFF_WKVH     53018624LL    // 2M halves
#define OFF_WPH      54067200LL    // 1M halves
#define OFF_PHIH     54591488LL    // 1M halves
#define OFF_WE1H     55115776LL    // 8M halves
#define OFF_WE2H     59310080LL    // 8M halves
#define OFF_QH       63504384LL    // 4M halves
#define OFF_KVH      65601536LL    // 8M halves
#define OFF_ATTOUTH  69795840LL    // 4M halves
#define OFF_X1H      71892992LL    // 4M halves
#define OFF_DISPTH   73990144LL    // 4M halves
#define OFF_COMBH    76087296LL    // 4M halves
#define OFF_SLOTSH   78184448LL    // 4M halves (4 batches x 1024x1024)
#define OFF_HH       80281600LL    // 16M halves (8 batches x 512x4096)
#define OFF_YMOEH    88670208LL    // 4M halves (8 batches x 512x1024)
#define ARENA_FLOATS 90767360LL

__device__ float g_arena[ARENA_FLOATS];

__device__ __forceinline__ float gelu_tanh(float v) {
    const float c0 = 0.7978845608028654f;   // sqrt(2/pi)
    float t = tanhf(c0 * (v + 0.044715f * v * v * v));
    return 0.5f * v * (1.0f + t);
}

__device__ __forceinline__ uint32_t smem_u32(const void* p) {
    return (uint32_t)__cvta_generic_to_shared(p);
}

#define CP16(dst, src) \
    asm volatile("cp.async.cg.shared.global [%0], [%1], 16;" :: "r"(dst), "l"(src))
#define CP_COMMIT() asm volatile("cp.async.commit_group;")
#define CP_WAIT0()  asm volatile("cp.async.wait_group 0;")

#define MMA_F16(c0,c1,c2,c3,a0,a1,a2,a3,b0,b1)                                \
    asm volatile("mma.sync.aligned.m16n8k16.row.col.f32.f16.f16.f32 "         \
                 "{%0,%1,%2,%3},{%4,%5,%6,%7},{%8,%9},{%0,%1,%2,%3};"         \
                 : "+f"(c0), "+f"(c1), "+f"(c2), "+f"(c3)                     \
                 : "r"(a0), "r"(a1), "r"(a2), "r"(a3), "r"(b0), "r"(b1))

#define LDSM_X4(r0,r1,r2,r3,addr)                                             \
    asm volatile("ldmatrix.sync.aligned.m8n8.x4.shared.b16 {%0,%1,%2,%3}, [%4];" \
                 : "=r"(r0), "=r"(r1), "=r"(r2), "=r"(r3) : "r"(addr))

#define LDSM_X4_T(r0,r1,r2,r3,addr)                                           \
    asm volatile("ldmatrix.sync.aligned.m8n8.x4.trans.shared.b16 {%0,%1,%2,%3}, [%4];" \
                 : "=r"(r0), "=r"(r1), "=r"(r2), "=r"(r3) : "r"(addr))

// ---------------------------------------------------------------------------
// RNE-round a f32 buffer to fp16 (element count multiple of 4; n4 = count/4).
// ---------------------------------------------------------------------------
__global__ void round_h(const float* __restrict__ src, __half* __restrict__ dst, int n4)
{
    int i = blockIdx.x * blockDim.x + threadIdx.x;
    if (i < n4) {
        float4 v = ((const float4*)src)[i];
        __half2 h01 = __floats2half2_rn(v.x, v.y);
        __half2 h23 = __floats2half2_rn(v.z, v.w);
        uint2 o;
        o.x = *(uint32_t*)&h01;
        o.y = *(uint32_t*)&h23;
        ((uint2*)dst)[i] = o;
    }
}

// ---------------------------------------------------------------------------
// fp16 tensor-core batched GEMM (m16n8k16, fp32 accum).
// cp.async double-buffered static smem, k-tile 32.
// A fp16 [M,K] row-major, B fp16 [K,N] row-major. M,N mult 128, K mult 32.
// 8 warps (2x4), warp tile 64x32. A-frags via ldmatrix, B via ldmatrix.trans.
// Cf (f32) and/or Ch (fp16, RNE) outputs; act: 0 none, 1 +bias, 2 +bias+gelu.
// ---------------------------------------------------------------------------
__global__ void __launch_bounds__(256, 2)
hgemm(const __half* __restrict__ A, const __half* __restrict__ Bm,
      const float* __restrict__ bias, float* __restrict__ Cf,
      __half* __restrict__ Ch,
      int M, int N, int K,
      long long sA, long long sB, long long sBias, long long sC,
      int nBmod, int act)
{
    int z = blockIdx.z;
    int zb = nBmod ? (z % nBmod) : z;
    A  += (long long)z * sA;
    Bm += (long long)zb * sB;
    if (act >= 1) bias += (long long)zb * sBias;
    if (Cf) Cf += (long long)z * sC;
    if (Ch) Ch += (long long)z * sC;

    __shared__ __half As[2][128][40];   // [m][k32 pad 40] (80B rows, 16B-aligned)
    __shared__ __half Bs[2][32][136];   // [k][n128 pad 136] (272B rows, 16B-aligned)

    int bx = blockIdx.x, by = blockIdx.y;
    int tid = threadIdx.x;
    int wid = tid >> 5;
    int lane = tid & 31;
    int g = lane >> 2;
    int j = lane & 3;
    int wm64 = (wid >> 2) * 64;
    int wn32 = (wid & 3) * 32;

    // gmem->smem copy mapping (2 CP16 each for A and B per k32 tile)
    int aRow = tid >> 1;             // 0..127
    int aKc  = (tid & 1) * 16;       // 0 or 16 (fp16 units)
    int bRow = tid >> 3;             // 0..31
    int bCc  = (tid & 7) * 16;       // 0..112

    const __half* Ap = A + (long long)(by * 128 + aRow) * K + aKc;
    const __half* Bp = Bm + (long long)bRow * N + bx * 128 + bCc;

    uint32_t aSm = smem_u32(&As[0][aRow][aKc]);
    uint32_t bSm = smem_u32(&Bs[0][bRow][bCc]);
    const uint32_t A_BUF = 128 * 40 * 2;   // 10240 bytes
    const uint32_t B_BUF = 32 * 136 * 2;   // 8704 bytes

    // ldmatrix lane mapping
    int lmat = lane >> 3, lrow = lane & 7;
    // A frags: matrix i -> (+8 m-rows if i&1, +8 k if i>>1)
    uint32_t aFrag[4];
    #pragma unroll
    for (int mt = 0; mt < 4; mt++)
        aFrag[mt] = smem_u32(
            &As[0][wm64 + mt * 16 + (lmat & 1) * 8 + lrow][(lmat >> 1) * 8]);
    // B frags: matrix i -> (+8 k-rows if i&1, +8 n if i>>1); p selects n16 pair
    uint32_t bFrag[2];
    #pragma unroll
    for (int p = 0; p < 2; p++)
        bFrag[p] = smem_u32(
            &Bs[0][(lmat & 1) * 8 + lrow][wn32 + p * 16 + (lmat >> 1) * 8]);

    float c[4][4][4];
    #pragma unroll
    for (int mt = 0; mt < 4; mt++)
        #pragma unroll
        for (int nt = 0; nt < 4; nt++)
            #pragma unroll
            for (int r = 0; r < 4; r++) c[mt][nt][r] = 0.0f;

    // issue tile 0
    CP16(aSm, Ap);            CP16(aSm + 16, Ap + 8);
    CP16(bSm, Bp);            CP16(bSm + 16, Bp + 8);
    CP_COMMIT();

    int buf = 0;
    for (int k0 = 0; k0 < K; k0 += 32) {
        CP_WAIT0();
        __syncthreads();

        if (k0 + 32 < K) {
            Ap += 32;
            Bp += (long long)32 * N;
            uint32_t aD = aSm + (buf ^ 1) * A_BUF;
            uint32_t bD = bSm + (buf ^ 1) * B_BUF;
            CP16(aD, Ap);        CP16(aD + 16, Ap + 8);
            CP16(bD, Bp);        CP16(bD + 16, Bp + 8);
            CP_COMMIT();
        }

        uint32_t aB = (uint32_t)buf * A_BUF;
        uint32_t bB = (uint32_t)buf * B_BUF;

        #pragma unroll
        for (int kk = 0; kk < 32; kk += 16) {
            uint32_t a[4][4];
            uint32_t bfr[4][2];
            #pragma unroll
            for (int mt = 0; mt < 4; mt++)
                LDSM_X4(a[mt][0], a[mt][1], a[mt][2], a[mt][3],
                        aFrag[mt] + aB + kk * 2);
            #pragma unroll
            for (int p = 0; p < 2; p++)
                LDSM_X4_T(bfr[2 * p][0], bfr[2 * p][1],
                          bfr[2 * p + 1][0], bfr[2 * p + 1][1],
                          bFrag[p] + bB + kk * 272);
            #pragma unroll
            for (int mt = 0; mt < 4; mt++)
                #pragma unroll
                for (int nt = 0; nt < 4; nt++)
                    MMA_F16(c[mt][nt][0], c[mt][nt][1], c[mt][nt][2], c[mt][nt][3],
                            a[mt][0], a[mt][1], a[mt][2], a[mt][3],
                            bfr[nt][0], bfr[nt][1]);
        }
        buf ^= 1;
    }

    // epilogue
    #pragma unroll
    for (int mt = 0; mt < 4; mt++) {
        int r0 = by * 128 + wm64 + mt * 16 + g;
        #pragma unroll
        for (int nt = 0; nt < 4; nt++) {
            int col = bx * 128 + wn32 + nt * 8 + 2 * j;
            float b0 = 0.0f, b1 = 0.0f;
            if (act >= 1) { b0 = bias[col]; b1 = bias[col + 1]; }
            float v0 = c[mt][nt][0] + b0;
            float v1 = c[mt][nt][1] + b1;
            float v2 = c[mt][nt][2] + b0;
            float v3 = c[mt][nt][3] + b1;
            if (act == 2) {
                v0 = gelu_tanh(v0); v1 = gelu_tanh(v1);
                v2 = gelu_tanh(v2); v3 = gelu_tanh(v3);
            }
            if (Cf) {
                *(float2*)(Cf + (long long)r0 * N + col)       = make_float2(v0, v1);
                *(float2*)(Cf + (long long)(r0 + 8) * N + col) = make_float2(v2, v3);
            }
            if (Ch) {
                __half2 h01 = __floats2half2_rn(v0, v1);
                __half2 h23 = __floats2half2_rn(v2, v3);
                *(uint32_t*)(Ch + (long long)r0 * N + col)       = *(uint32_t*)&h01;
                *(uint32_t*)(Ch + (long long)(r0 + 8) * N + col) = *(uint32_t*)&h23;
            }
        }
    }
}

// ---------------------------------------------------------------------------
// Fused attention (fp16 HMMA): per (b,h), n-tile 64.
// S = Q K^T (q/kv fp16); E = exp(0.125*S) -> fp16 (tmp + smem Ps);
// O = (E@V)/rowsum -> attout fp16. No max subtraction (logits small).
// All smem tiles pad-72 (144B rows): 16B-aligned uint4/ldmatrix access;
// LDS.32 frag reads hit banks 4g+j (conflict-free).
// ---------------------------------------------------------------------------
__global__ void __launch_bounds__(256)
att_fused(const __half* __restrict__ qh, const __half* __restrict__ kvh,
          __half* __restrict__ tmp, float* __restrict__ rowrl,
          __half* __restrict__ attouth)
{
    int bh = blockIdx.y;
    int b = bh >> 4, h = bh & 15;
    int n0 = blockIdx.x * 64;

    __shared__ __half Qs[64][72];   // [n][d]
    __shared__ __half Kt[64][72];   // [m][d]
    __shared__ __half Vs[64][72];   // [m][d]
    __shared__ __half Ps[64][72];   // [n][m-chunk]
    __shared__ float sums[4][64];

    int tid = threadIdx.x, lane = tid & 31, wid = tid >> 5;
    int g = lane >> 2, j = lane & 3;
    int wm32 = (wid >> 2) * 32;
    int wn16 = (wid & 3) * 16;

    sums[tid >> 6][tid & 63] = 0.0f;

    for (int i = tid; i < 512; i += 256) {
        int r = i >> 3, seg = (i & 7) * 8;
        *(uint4*)&Qs[r][seg] =
            *(const uint4*)(qh + ((size_t)(b * 1024 + n0 + r) * 1024) + h * 64 + seg);
    }

    // V B-frag ldmatrix base (n-dim = d, warp covers wn16 .. wn16+15)
    int lmat = lane >> 3, lrow = lane & 7;
    uint32_t vFrag = smem_u32(&Vs[(lmat & 1) * 8 + lrow][wn16 + (lmat >> 1) * 8]);

    float o[2][2][4];
    #pragma unroll
    for (int mt = 0; mt < 2; mt++)
        #pragma unroll
        for (int nt = 0; nt < 2; nt++)
            #pragma unroll
            for (int r = 0; r < 4; r++) o[mt][nt][r] = 0.0f;

    for (int m0 = 0; m0 < 1024; m0 += 64) {
        __syncthreads();
        for (int i = tid; i < 512; i += 256) {
            int r = i >> 3, seg = (i & 7) * 8;
            const __half* kb = kvh + ((size_t)(b * 1024 + m0 + r) * 2048) + h * 64 + seg;
            *(uint4*)&Kt[r][seg] = *(const uint4*)kb;
            *(uint4*)&Vs[r][seg] = *(const uint4*)(kb + 1024);
        }
        __syncthreads();

        // S-mma: A = Qs, B = Kt (k-contiguous fp16 pairs -> LDS.32)
        float c[2][2][4];
        #pragma unroll
        for (int mt = 0; mt < 2; mt++)
            #pragma unroll
            for (int nt = 0; nt < 2; nt++)
                #pragma unroll
                for (int r = 0; r < 4; r++) c[mt][nt][r] = 0.0f;

        #pragma unroll
        for (int kk = 0; kk < 64; kk += 16) {
            uint32_t a[2][4], bf[2][2];
            #pragma unroll
            for (int mt = 0; mt < 2; mt++) {
                const __half* p0 = &Qs[wm32 + mt * 16 + g][kk + 2 * j];
                a[mt][0] = *(const uint32_t*)p0;
                a[mt][1] = *(const uint32_t*)(p0 + 8 * 72);
                a[mt][2] = *(const uint32_t*)(p0 + 8);
                a[mt][3] = *(const uint32_t*)(p0 + 8 * 72 + 8);
            }
            #pragma unroll
            for (int nt = 0; nt < 2; nt++) {
                const __half* p0 = &Kt[wn16 + nt * 8 + g][kk + 2 * j];
                bf[nt][0] = *(const uint32_t*)p0;
                bf[nt][1] = *(const uint32_t*)(p0 + 8);
            }
            #pragma unroll
            for (int mt = 0; mt < 2; mt++)
                #pragma unroll
                for (int nt = 0; nt < 2; nt++)
                    MMA_F16(c[mt][nt][0], c[mt][nt][1], c[mt][nt][2], c[mt][nt][3],
                            a[mt][0], a[mt][1], a[mt][2], a[mt][3],
                            bf[nt][0], bf[nt][1]);
        }

        // E = exp(0.125*S) -> fp16 (tmp, Ps); row sums of the fp16 values
        #pragma unroll
        for (int mt = 0; mt < 2; mt++) {
            int r1 = wm32 + mt * 16 + g;
            float eA = 0.0f, eB = 0.0f;
            #pragma unroll
            for (int nt = 0; nt < 2; nt++) {
                int col = wn16 + nt * 8 + 2 * j;
                float e0 = __expf(0.125f * c[mt][nt][0]);
                float e1 = __expf(0.125f * c[mt][nt][1]);
                float e2 = __expf(0.125f * c[mt][nt][2]);
                float e3 = __expf(0.125f * c[mt][nt][3]);
                __half2 h01 = __floats2half2_rn(e0, e1);
                __half2 h23 = __floats2half2_rn(e2, e3);
                size_t idx = ((size_t)bh * 1024 + n0 + r1) * 1024 + m0 + col;
                __stcs((unsigned int*)(tmp + idx),            *(uint32_t*)&h01);
                __stcs((unsigned int*)(tmp + idx + 8 * 1024), *(uint32_t*)&h23);
                *(uint32_t*)&Ps[r1][col]     = *(uint32_t*)&h01;
                *(uint32_t*)&Ps[r1 + 8][col] = *(uint32_t*)&h23;
                float2 f01 = __half22float2(h01);
                float2 f23 = __half22float2(h23);
                eA += f01.x + f01.y;
                eB += f23.x + f23.y;
            }
            eA += __shfl_xor_sync(0xffffffffu, eA, 1);
            eA += __shfl_xor_sync(0xffffffffu, eA, 2);
            eB += __shfl_xor_sync(0xffffffffu, eB, 1);
            eB += __shfl_xor_sync(0xffffffffu, eB, 2);
            if (j == 0) {
                sums[wn16 >> 4][r1]     += eA;
                sums[wn16 >> 4][r1 + 8] += eB;
            }
        }
        __syncthreads();

        // PV-mma: A = Ps (LDS.32 pairs), B = Vs (ldmatrix.trans)
        #pragma unroll
        for (int kk = 0; kk < 64; kk += 16) {
            uint32_t a[2][4], bf[2][2];
            #pragma unroll
            for (int mt = 0; mt < 2; mt++) {
                const __half* p0 = &Ps[wm32 + mt * 16 + g][kk + 2 * j];
                a[mt][0] = *(const uint32_t*)p0;
                a[mt][1] = *(const uint32_t*)(p0 + 8 * 72);
                a[mt][2] = *(const uint32_t*)(p0 + 8);
                a[mt][3] = *(const uint32_t*)(p0 + 8 * 72 + 8);
            }
            LDSM_X4_T(bf[0][0], bf[0][1], bf[1][0], bf[1][1],
                      vFrag + kk * 144);
            #pragma unroll
            for (int mt = 0; mt < 2; mt++)
                #pragma unroll
                for (int nt = 0; nt < 2; nt++)
                    MMA_F16(o[mt][nt][0], o[mt][nt][1], o[mt][nt][2], o[mt][nt][3],
                            a[mt][0], a[mt][1], a[mt][2], a[mt][3],
                            bf[nt][0], bf[nt][1]);
        }
    }

    __syncthreads();
    if (tid < 64) {
        float tot = sums[0][tid] + sums[1][tid] + sums[2][tid] + sums[3][tid];
        float r = 1.0f / tot;
        sums[0][tid] = r;
        rowrl[(size_t)bh * 1024 + n0 + tid] = r;
    }
    __syncthreads();

    #pragma unroll
    for (int mt = 0; mt < 2; mt++) {
        int r1 = wm32 + mt * 16 + g;
        float rlA = sums[0][r1], rlB = sums[0][r1 + 8];
        #pragma unroll
        for (int nt = 0; nt < 2; nt++) {
            int col = wn16 + nt * 8 + 2 * j;
            __half* base = attouth + ((size_t)(b * 1024 + n0 + r1) * 1024) + h * 64 + col;
            __half2 h01 = __floats2half2_rn(o[mt][nt][0] * rlA, o[mt][nt][1] * rlA);
            __half2 h23 = __floats2half2_rn(o[mt][nt][2] * rlB, o[mt][nt][3] * rlB);
            *(uint32_t*)base              = *(uint32_t*)&h01;
            *(uint32_t*)(base + 8 * 1024) = *(uint32_t*)&h23;
        }
    }
}

// ---------------------------------------------------------------------------
// Normalize + transpose: out(b,n,m,h) = E_fp16(b,h,n,m) * rl(b,h,n).
// ---------------------------------------------------------------------------
__global__ void attn_tr(const __half* __restrict__ tmp, const float* __restrict__ rowrl,
                        float* __restrict__ outAttn)
{
    int b = blockIdx.z;
    int n = blockIdx.y;
    int m0 = blockIdx.x * 256;
    __shared__ float T[16][257];
    __shared__ float rl_s[16];
    int tid = threadIdx.x;
    if (tid < 16) rl_s[tid] = rowrl[(size_t)(b * 16 + tid) * 1024 + n];
    __syncthreads();
    for (int i = tid; i < 16 * 128; i += 256) {
        int hh = i >> 7, mm = (i & 127) * 2;
        unsigned int raw = __ldcs((const unsigned int*)
            (tmp + ((size_t)(b * 16 + hh) * 1024 + n) * 1024 + m0 + mm));
        __half2 v = *(__half2*)&raw;
        float2 f = __half22float2(v);
        float rl = rl_s[hh];
        T[hh][mm]     = f.x * rl;
        T[hh][mm + 1] = f.y * rl;
    }
    __syncthreads();
    float* dst = outAttn + ((size_t)(b * 1024 + n) * 1024 + m0 + tid) * 16;
    #pragma unroll
    for (int k = 0; k < 16; k += 4) {
        __stcs((float4*)(dst + k),
               make_float4(T[k][tid], T[k + 1][tid], T[k + 2][tid], T[k + 3][tid]));
    }
}

// ---------------------------------------------------------------------------
// Row softmax over contiguous 1024 (combine weights), fp16 out.
// ---------------------------------------------------------------------------
__global__ void row_softmax(const float* __restrict__ in, __half* __restrict__ outp)
{
    size_t row = blockIdx.x;
    const float4* L = (const float4*)(in + row * 1024);
    int t = threadIdx.x;
    float4 v = L[t];
    float mx = fmaxf(fmaxf(v.x, v.y), fmaxf(v.z, v.w));
    __shared__ float smA[8], smB[8];
    #pragma unroll
    for (int off = 16; off; off >>= 1) mx = fmaxf(mx, __shfl_xor_sync(0xffffffffu, mx, off));
    if ((t & 31) == 0) smA[t >> 5] = mx;
    __syncthreads();
    mx = smA[0];
    #pragma unroll
    for (int w = 1; w < 8; w++) mx = fmaxf(mx, smA[w]);
    float e0 = __expf(v.x - mx), e1 = __expf(v.y - mx);
    float e2 = __expf(v.z - mx), e3 = __expf(v.w - mx);
    float s = e0 + e1 + e2 + e3;
    #pragma unroll
    for (int off = 16; off; off >>= 1) s += __shfl_xor_sync(0xffffffffu, s, off);
    if ((t & 31) == 0) smB[t >> 5] = s;
    __syncthreads();
    s = 0.0f;
    #pragma unroll
    for (int w = 0; w < 8; w++) s += smB[w];
    float r = 1.0f / s;
    __half2 h01 = __floats2half2_rn(e0 * r, e1 * r);
    __half2 h23 = __floats2half2_rn(e2 * r, e3 * r);
    uint2 o;
    o.x = *(uint32_t*)&h01;
    o.y = *(uint32_t*)&h23;
    ((uint2*)(outp + row * 1024))[t] = o;
}

// ---------------------------------------------------------------------------
// Dispatch softmax over token axis n, written TRANSPOSED, fp16 out.
// ---------------------------------------------------------------------------
__global__ void disp_softmax(const float* __restrict__ logits, __half* __restrict__ dispT)
{
    int b = blockIdx.y;
    int c0 = blockIdx.x * 64;
    const float* L = logits + (size_t)b * 1048576;
    __half* O = dispT + (size_t)b * 1048576;
    int tid = threadIdx.x;
    int tx = tid & 63, ty = tid >> 6;   // 4 x 64
    int col = c0 + tx;

    __shared__ float red[4][64];
    float mx = -1e30f;
    for (int n = ty; n < 1024; n += 4) mx = fmaxf(mx, L[(size_t)n * 1024 + col]);
    red[ty][tx] = mx;
    __syncthreads();
    mx = fmaxf(fmaxf(red[0][tx], red[1][tx]), fmaxf(red[2][tx], red[3][tx]));
    __syncthreads();
    float s = 0.0f;
    for (int n = ty; n < 1024; n += 4) s += __expf(L[(size_t)n * 1024 + col] - mx);
    red[ty][tx] = s;
    __syncthreads();
    s = red[0][tx] + red[1][tx] + red[2][tx] + red[3][tx];
    float rinv = 1.0f / s;
    __syncthreads();

    __shared__ float T[64][65];
    for (int n0 = 0; n0 < 1024; n0 += 64) {
        for (int n = ty; n < 64; n += 4)
            T[tx][n] = __expf(L[(size_t)(n0 + n) * 1024 + col] - mx) * rinv;
        __syncthreads();
        int cl = tid >> 2;
        int nl = (tid & 3) * 16;
        __half* dst = O + (size_t)(c0 + cl) * 1024 + n0 + nl;
        #pragma unroll
        for (int k = 0; k < 16; k += 4) {
            __half2 h01 = __floats2half2_rn(T[cl][nl + k],     T[cl][nl + k + 1]);
            __half2 h23 = __floats2half2_rn(T[cl][nl + k + 2], T[cl][nl + k + 3]);
            uint2 o;
            o.x = *(uint32_t*)&h01;
            o.y = *(uint32_t*)&h23;
            *(uint2*)(dst + k) = o;
        }
        __syncthreads();
    }
}

// ---------------------------------------------------------------------------
// Fused residual + LayerNorm: out = LN(a + coefb * bsrc) * g + beta.
// If outH != null: values RNE-rounded to fp16, written to BOTH outp (f32)
// and outH (fp16) so GEMM inputs == residual values exactly.
// ---------------------------------------------------------------------------
__global__ void ln_res(const float* __restrict__ a, const float* __restrict__ bsrc,
                       float coefb, const float* __restrict__ g,
                       const float* __restrict__ beta, float* __restrict__ outp,
                       __half* __restrict__ outH)
{
    size_t row = blockIdx.x;
    int t = threadIdx.x;
    float4 av = ((const float4*)(a + row * 1024))[t];
    float4 bv = ((const float4*)(bsrc + row * 1024))[t];
    float x0 = av.x + coefb * bv.x;
    float x1 = av.y + coefb * bv.y;
    float x2 = av.z + coefb * bv.z;
    float x3 = av.w + coefb * bv.w;
    float s = x0 + x1 + x2 + x3;
    float q = x0 * x0 + x1 * x1 + x2 * x2 + x3 * x3;
    __shared__ float smA[8], smB[8];
    #pragma unroll
    for (int off = 16; off; off >>= 1) {
        s += __shfl_xor_sync(0xffffffffu, s, off);
        q += __shfl_xor_sync(0xffffffffu, q, off);
    }
    if ((t & 31) == 0) { smA[t >> 5] = s; smB[t >> 5] = q; }
    __syncthreads();
    s = 0.0f; q = 0.0f;
    #pragma unroll
    for (int w = 0; w < 8; w++) { s += smA[w]; q += smB[w]; }
    float mu = s * (1.0f / 1024.0f);
    float var = q * (1.0f / 1024.0f) - mu * mu;
    float rs = rsqrtf(var + 1e-5f);
    float4 gv = ((const float4*)g)[t];
    float4 btv = ((const float4*)beta)[t];
    float4 out4;
    out4.x = (x0 - mu) * rs * gv.x + btv.x;
    out4.y = (x1 - mu) * rs * gv.y + btv.y;
    out4.z = (x2 - mu) * rs * gv.z + btv.z;
    out4.w = (x3 - mu) * rs * gv.w + btv.w;
    if (outH) {
        __half2 h01 = __floats2half2_rn(out4.x, out4.y);
        __half2 h23 = __floats2half2_rn(out4.z, out4.w);
        uint2 o;
        o.x = *(uint32_t*)&h01;
        o.y = *(uint32_t*)&h23;
        ((uint2*)(outH + row * 1024))[t] = o;
        float2 f01 = __half22float2(h01);
        float2 f23 = __half22float2(h23);
        out4.x = f01.x; out4.y = f01.y; out4.z = f23.x; out4.w = f23.y;
    }
    ((float4*)(outp + row * 1024))[t] = out4;
}

// ---------------------------------------------------------------------------
// Launcher
// ---------------------------------------------------------------------------
extern "C" void kernel_launch(void* const* d_in, const int* in_sizes, int n_in,
                              void* d_out, int out_size)
{
    const float* x   = (const float*)d_in[0];
    const float* Wq  = (const float*)d_in[1];
    const float* bq  = (const float*)d_in[2];
    const float* Wkv = (const float*)d_in[3];
    const float* bkv = (const float*)d_in[4];
    const float* Wp  = (const float*)d_in[5];
    const float* bp  = (const float*)d_in[6];
    const float* g1  = (const float*)d_in[7];
    const float* b1  = (const float*)d_in[8];
    const float* phi = (const float*)d_in[9];
    const float* We1 = (const float*)d_in[10];
    const float* be1 = (const float*)d_in[11];
    const float* We2 = (const float*)d_in[12];
    const float* be2 = (const float*)d_in[13];
    const float* g2  = (const float*)d_in[14];
    const float* b2  = (const float*)d_in[15];

    float* arena = nullptr;
    cudaGetSymbolAddress((void**)&arena, g_arena);

    __half* tmp     = (__half*)(arena + OFF_TMP);
    float*  proj    = arena + OFF_PROJ;
    float*  x1      = arena + OFF_X1;
    float*  logits  = arena + OFF_LOGITS;
    float*  moeout  = arena + OFF_MOE;
    float*  rl      = arena + OFF_RL;
    __half* xh      = (__half*)(arena + OFF_XH);
    __half* Wqh     = (__half*)(arena + OFF_WQH);
    __half* Wkvh    = (__half*)(arena + OFF_WKVH);
    __half* Wph     = (__half*)(arena + OFF_WPH);
    __half* phih    = (__half*)(arena + OFF_PHIH);
    __half* We1h    = (__half*)(arena + OFF_WE1H);
    __half* We2h    = (__half*)(arena + OFF_WE2H);
    __half* qh      = (__half*)(arena + OFF_QH);
    __half* kvh     = (__half*)(arena + OFF_KVH);
    __half* attouth = (__half*)(arena + OFF_ATTOUTH);
    __half* x1h     = (__half*)(arena + OFF_X1H);
    __half* dispTh  = (__half*)(arena + OFF_DISPTH);
    __half* combh   = (__half*)(arena + OFF_COMBH);
    __half* slotsh  = (__half*)(arena + OFF_SLOTSH);
    __half* hh      = (__half*)(arena + OFF_HH);
    __half* ymoeh   = (__half*)(arena + OFF_YMOEH);

    float* out = (float*)d_out;
    float* outAttn = out + 4194304;

    dim3 T(256);

    // prep: RNE-round harness inputs that feed GEMMs to fp16
    round_h<<<4096, T>>>(x,   xh,   1048576);
    round_h<<<1024, T>>>(Wq,  Wqh,   262144);
    round_h<<<2048, T>>>(Wkv, Wkvh,  524288);
    round_h<<<1024, T>>>(Wp,  Wph,   262144);
    round_h<<<1024, T>>>(phi, phih,  262144);
    round_h<<<8192, T>>>(We1, We1h, 2097152);
    round_h<<<8192, T>>>(We2, We2h, 2097152);

    // q = x @ Wq + bq          (4096x1024x1024) -> fp16
    hgemm<<<dim3(8, 32, 1), T>>>(xh, Wqh, bq, nullptr, qh, 4096, 1024, 1024,
                                 0, 0, 0, 0, 1, 1);
    // kv = x @ Wkv + bkv       (4096x2048x1024) -> fp16
    hgemm<<<dim3(16, 32, 1), T>>>(xh, Wkvh, bkv, nullptr, kvh, 4096, 2048, 1024,
                                  0, 0, 0, 0, 1, 1);

    // fused attention + transpose
    att_fused<<<dim3(16, 64), T>>>(qh, kvh, tmp, rl, attouth);
    attn_tr<<<dim3(4, 1024, 4), T>>>(tmp, rl, outAttn);

    // out-proj (f32) + residual LN (x1 f32 + fp16)
    hgemm<<<dim3(8, 32, 1), T>>>(attouth, Wph, bp, proj, nullptr, 4096, 1024, 1024,
                                 0, 0, 0, 0, 1, 1);
    ln_res<<<4096, T>>>(proj, x, 1.0f, g1, b1, x1, x1h);

    // soft-MoE
    hgemm<<<dim3(8, 32, 1), T>>>(x1h, phih, nullptr, logits, nullptr, 4096, 1024, 1024,
                                 0, 0, 0, 0, 1, 0);
    row_softmax<<<4096, T>>>(logits, combh);
    disp_softmax<<<dim3(16, 4), T>>>(logits, dispTh);

    // slots[b] = dispT[b] @ x1[b] -> fp16
    hgemm<<<dim3(8, 8, 4), T>>>(dispTh, x1h, nullptr, nullptr, slotsh, 1024, 1024, 1024,
                                1048576, 1048576, 0, 1048576, 0, 0);
    // h = gelu(slots @ We1[e] + be1[e]) -> fp16
    hgemm<<<dim3(32, 4, 8), T>>>(slotsh, We1h, be1, nullptr, hh, 512, 4096, 1024,
                                 524288, 4194304, 4096, 2097152, 2, 2);
    // y = h @ We2[e] + be2[e] -> fp16
    hgemm<<<dim3(8, 4, 8), T>>>(hh, We2h, be2, nullptr, ymoeh, 512, 1024, 4096,
                                2097152, 4194304, 1024, 524288, 2, 1);
    // moe_out[b] = comb[b] @ ymoe[b] -> f32
    hgemm<<<dim3(8, 8, 4), T>>>(combh, ymoeh, nullptr, moeout, nullptr, 1024, 1024, 1024,
                                1048576, 1048576, 0, 1048576, 0, 0);

    // y = LN(moe_out + 2*x1)
    ln_res<<<4096, T>>>(moeout, x1, 2.0f, g2, b2, out, nullptr);
}

// round 12
// speedup vs baseline: 1.9462x; 1.0223x over previous
#include <cuda_runtime.h>
#include <cuda_fp16.h>
#include <math.h>
#include <stdint.h>

// ---------------------------------------------------------------------------
// Problem constants
//   B=4, SEQ=1024, DIM=1024, HEADS=16, N_EXP=2, SLOTS=512, HID=4096
// Output: [ y : 4*1024*1024 f32 ][ attn : 4*1024*1024*16 f32 ]
// All GEMM/attention operands fp16 (RNE-rounded at producer), fp32 accumulate.
// ---------------------------------------------------------------------------

// arena offsets in FLOAT units (fp16 buffers occupy elem_count/2 float slots)
#define OFF_TMP      0LL           // 64M halves = 32M floats
#define OFF_PROJ     33554432LL    // 4M f32
#define OFF_X1       37748736LL    // 4M f32
#define OFF_LOGITS   41943040LL    // 4M f32
#define OFF_MOE      46137344LL    // 4M f32
#define OFF_RL       50331648LL    // 64K f32
#define OFF_XH       50397184LL    // 4M halves
#define OFF_WQH      52494336LL    // 1M halves
#define OFF_WKVH     53018624LL    // 2M halves
#define OFF_WPH      54067200LL    // 1M halves
#define OFF_PHIH     54591488LL    // 1M halves
#define OFF_WE1H     55115776LL    // 8M halves
#define OFF_WE2H     59310080LL    // 8M halves
#define OFF_QH       63504384LL    // 4M halves
#define OFF_KVH      65601536LL    // 8M halves
#define OFF_ATTOUTH  69795840LL    // 4M halves
#define OFF_X1H      71892992LL    // 4M halves
#define OFF_DISPTH   73990144LL    // 4M halves
#define OFF_COMBH    76087296LL    // 4M halves
#define OFF_SLOTSH   78184448LL    // 4M halves (4 batches x 1024x1024)
#define OFF_HH       80281600LL    // 16M halves (8 batches x 512x4096)
#define OFF_YMOEH    88670208LL    // 4M halves (8 batches x 512x1024)
#define ARENA_FLOATS 90767360LL

__device__ float g_arena[ARENA_FLOATS];

__device__ __forceinline__ float gelu_tanh(float v) {
    const float c0 = 0.7978845608028654f;   // sqrt(2/pi)
    float t = tanhf(c0 * (v + 0.044715f * v * v * v));
    return 0.5f * v * (1.0f + t);
}

__device__ __forceinline__ uint32_t smem_u32(const void* p) {
    return (uint32_t)__cvta_generic_to_shared(p);
}

#define CP16(dst, src) \
    asm volatile("cp.async.cg.shared.global [%0], [%1], 16;" :: "r"(dst), "l"(src))
#define CP_COMMIT() asm volatile("cp.async.commit_group;")
#define CP_WAIT0()  asm volatile("cp.async.wait_group 0;")

#define MMA_F16(c0,c1,c2,c3,a0,a1,a2,a3,b0,b1)                                \
    asm volatile("mma.sync.aligned.m16n8k16.row.col.f32.f16.f16.f32 "         \
                 "{%0,%1,%2,%3},{%4,%5,%6,%7},{%8,%9},{%0,%1,%2,%3};"         \
                 : "+f"(c0), "+f"(c1), "+f"(c2), "+f"(c3)                     \
                 : "r"(a0), "r"(a1), "r"(a2), "r"(a3), "r"(b0), "r"(b1))

#define LDSM_X4(r0,r1,r2,r3,addr)                                             \
    asm volatile("ldmatrix.sync.aligned.m8n8.x4.shared.b16 {%0,%1,%2,%3}, [%4];" \
                 : "=r"(r0), "=r"(r1), "=r"(r2), "=r"(r3) : "r"(addr))

#define LDSM_X4_T(r0,r1,r2,r3,addr)                                           \
    asm volatile("ldmatrix.sync.aligned.m8n8.x4.trans.shared.b16 {%0,%1,%2,%3}, [%4];" \
                 : "=r"(r0), "=r"(r1), "=r"(r2), "=r"(r3) : "r"(addr))

// ---------------------------------------------------------------------------
// RNE-round all seven GEMM input buffers f32 -> fp16 in ONE launch.
// Segment sizes in float4 units:
//   x 1048576 | Wq 262144 | Wkv 524288 | Wp 262144 | phi 262144
//   We1 2097152 | We2 2097152   (total 6553600)
// ---------------------------------------------------------------------------
__global__ void round_all(const float* __restrict__ x,  const float* __restrict__ Wq,
                          const float* __restrict__ Wkv,const float* __restrict__ Wp,
                          const float* __restrict__ phi,const float* __restrict__ We1,
                          const float* __restrict__ We2,
                          __half* __restrict__ xh,  __half* __restrict__ Wqh,
                          __half* __restrict__ Wkvh,__half* __restrict__ Wph,
                          __half* __restrict__ phih,__half* __restrict__ We1h,
                          __half* __restrict__ We2h)
{
    long long i = (long long)blockIdx.x * blockDim.x + threadIdx.x;
    const float* s; __half* d; long long off;
    if      (i < 1048576LL) { s = x;   d = xh;   off = i; }
    else if (i < 1310720LL) { s = Wq;  d = Wqh;  off = i - 1048576LL; }
    else if (i < 1835008LL) { s = Wkv; d = Wkvh; off = i - 1310720LL; }
    else if (i < 2097152LL) { s = Wp;  d = Wph;  off = i - 1835008LL; }
    else if (i < 2359296LL) { s = phi; d = phih; off = i - 2097152LL; }
    else if (i < 4456448LL) { s = We1; d = We1h; off = i - 2359296LL; }
    else if (i < 6553600LL) { s = We2; d = We2h; off = i - 4456448LL; }
    else return;
    float4 v = ((const float4*)s)[off];
    __half2 h01 = __floats2half2_rn(v.x, v.y);
    __half2 h23 = __floats2half2_rn(v.z, v.w);
    uint2 o;
    o.x = *(uint32_t*)&h01;
    o.y = *(uint32_t*)&h23;
    ((uint2*)d)[off] = o;
}

// ---------------------------------------------------------------------------
// fp16 tensor-core batched GEMM (m16n8k16, fp32 accum).
// cp.async double-buffered static smem, k-tile 32.
// A fp16 [M,K] row-major, B fp16 [K,N] row-major. M,N mult 128, K mult 32.
// 8 warps (2x4), warp tile 64x32. A-frags via ldmatrix, B via ldmatrix.trans.
// Cf (f32) and/or Ch (fp16, RNE) outputs; act: 0 none, 1 +bias, 2 +bias+gelu.
// ---------------------------------------------------------------------------
__global__ void __launch_bounds__(256, 2)
hgemm(const __half* __restrict__ A, const __half* __restrict__ Bm,
      const float* __restrict__ bias, float* __restrict__ Cf,
      __half* __restrict__ Ch,
      int M, int N, int K,
      long long sA, long long sB, long long sBias, long long sC,
      int nBmod, int act)
{
    int z = blockIdx.z;
    int zb = nBmod ? (z % nBmod) : z;
    A  += (long long)z * sA;
    Bm += (long long)zb * sB;
    if (act >= 1) bias += (long long)zb * sBias;
    if (Cf) Cf += (long long)z * sC;
    if (Ch) Ch += (long long)z * sC;

    __shared__ __half As[2][128][40];   // [m][k32 pad 40] (80B rows, 16B-aligned)
    __shared__ __half Bs[2][32][136];   // [k][n128 pad 136] (272B rows, 16B-aligned)

    int bx = blockIdx.x, by = blockIdx.y;
    int tid = threadIdx.x;
    int wid = tid >> 5;
    int lane = tid & 31;
    int g = lane >> 2;
    int j = lane & 3;
    int wm64 = (wid >> 2) * 64;
    int wn32 = (wid & 3) * 32;

    // gmem->smem copy mapping (2 CP16 each for A and B per k32 tile)
    int aRow = tid >> 1;             // 0..127
    int aKc  = (tid & 1) * 16;       // 0 or 16 (fp16 units)
    int bRow = tid >> 3;             // 0..31
    int bCc  = (tid & 7) * 16;       // 0..112

    const __half* Ap = A + (long long)(by * 128 + aRow) * K + aKc;
    const __half* Bp = Bm + (long long)bRow * N + bx * 128 + bCc;

    uint32_t aSm = smem_u32(&As[0][aRow][aKc]);
    uint32_t bSm = smem_u32(&Bs[0][bRow][bCc]);
    const uint32_t A_BUF = 128 * 40 * 2;   // 10240 bytes
    const uint32_t B_BUF = 32 * 136 * 2;   // 8704 bytes

    // ldmatrix lane mapping
    int lmat = lane >> 3, lrow = lane & 7;
    // A frags: matrix i -> (+8 m-rows if i&1, +8 k if i>>1)
    uint32_t aFrag[4];
    #pragma unroll
    for (int mt = 0; mt < 4; mt++)
        aFrag[mt] = smem_u32(
            &As[0][wm64 + mt * 16 + (lmat & 1) * 8 + lrow][(lmat >> 1) * 8]);
    // B frags: matrix i -> (+8 k-rows if i&1, +8 n if i>>1); p selects n16 pair
    uint32_t bFrag[2];
    #pragma unroll
    for (int p = 0; p < 2; p++)
        bFrag[p] = smem_u32(
            &Bs[0][(lmat & 1) * 8 + lrow][wn32 + p * 16 + (lmat >> 1) * 8]);

    float c[4][4][4];
    #pragma unroll
    for (int mt = 0; mt < 4; mt++)
        #pragma unroll
        for (int nt = 0; nt < 4; nt++)
            #pragma unroll
            for (int r = 0; r < 4; r++) c[mt][nt][r] = 0.0f;

    // issue tile 0
    CP16(aSm, Ap);            CP16(aSm + 16, Ap + 8);
    CP16(bSm, Bp);            CP16(bSm + 16, Bp + 8);
    CP_COMMIT();

    int buf = 0;
    for (int k0 = 0; k0 < K; k0 += 32) {
        CP_WAIT0();
        __syncthreads();

        if (k0 + 32 < K) {
            Ap += 32;
            Bp += (long long)32 * N;
            uint32_t aD = aSm + (buf ^ 1) * A_BUF;
            uint32_t bD = bSm + (buf ^ 1) * B_BUF;
            CP16(aD, Ap);        CP16(aD + 16, Ap + 8);
            CP16(bD, Bp);        CP16(bD + 16, Bp + 8);
            CP_COMMIT();
        }

        uint32_t aB = (uint32_t)buf * A_BUF;
        uint32_t bB = (uint32_t)buf * B_BUF;

        #pragma unroll
        for (int kk = 0; kk < 32; kk += 16) {
            uint32_t a[4][4];
            uint32_t bfr[4][2];
            #pragma unroll
            for (int mt = 0; mt < 4; mt++)
                LDSM_X4(a[mt][0], a[mt][1], a[mt][2], a[mt][3],
                        aFrag[mt] + aB + kk * 2);
            #pragma unroll
            for (int p = 0; p < 2; p++)
                LDSM_X4_T(bfr[2 * p][0], bfr[2 * p][1],
                          bfr[2 * p + 1][0], bfr[2 * p + 1][1],
                          bFrag[p] + bB + kk * 272);
            #pragma unroll
            for (int mt = 0; mt < 4; mt++)
                #pragma unroll
                for (int nt = 0; nt < 4; nt++)
                    MMA_F16(c[mt][nt][0], c[mt][nt][1], c[mt][nt][2], c[mt][nt][3],
                            a[mt][0], a[mt][1], a[mt][2], a[mt][3],
                            bfr[nt][0], bfr[nt][1]);
        }
        buf ^= 1;
    }

    // epilogue
    #pragma unroll
    for (int mt = 0; mt < 4; mt++) {
        int r0 = by * 128 + wm64 + mt * 16 + g;
        #pragma unroll
        for (int nt = 0; nt < 4; nt++) {
            int col = bx * 128 + wn32 + nt * 8 + 2 * j;
            float b0 = 0.0f, b1 = 0.0f;
            if (act >= 1) { b0 = bias[col]; b1 = bias[col + 1]; }
            float v0 = c[mt][nt][0] + b0;
            float v1 = c[mt][nt][1] + b1;
            float v2 = c[mt][nt][2] + b0;
            float v3 = c[mt][nt][3] + b1;
            if (act == 2) {
                v0 = gelu_tanh(v0); v1 = gelu_tanh(v1);
                v2 = gelu_tanh(v2); v3 = gelu_tanh(v3);
            }
            if (Cf) {
                *(float2*)(Cf + (long long)r0 * N + col)       = make_float2(v0, v1);
                *(float2*)(Cf + (long long)(r0 + 8) * N + col) = make_float2(v2, v3);
            }
            if (Ch) {
                __half2 h01 = __floats2half2_rn(v0, v1);
                __half2 h23 = __floats2half2_rn(v2, v3);
                *(uint32_t*)(Ch + (long long)r0 * N + col)       = *(uint32_t*)&h01;
                *(uint32_t*)(Ch + (long long)(r0 + 8) * N + col) = *(uint32_t*)&h23;
            }
        }
    }
}

// ---------------------------------------------------------------------------
// Fused attention (fp16 HMMA): per (b,h), n-tile 64.
// S = Q K^T (q/kv fp16); E = exp(0.125*S) -> fp16 (tmp + smem Ps);
// O = (E@V)/rowsum -> attout fp16. No max subtraction (logits small).
// All smem tiles pad-72 (144B rows): 16B-aligned uint4/ldmatrix access;
// LDS.32 frag reads hit banks 4g+j (conflict-free).
// ---------------------------------------------------------------------------
__global__ void __launch_bounds__(256)
att_fused(const __half* __restrict__ qh, const __half* __restrict__ kvh,
          __half* __restrict__ tmp, float* __restrict__ rowrl,
          __half* __restrict__ attouth)
{
    int bh = blockIdx.y;
    int b = bh >> 4, h = bh & 15;
    int n0 = blockIdx.x * 64;

    __shared__ __half Qs[64][72];   // [n][d]
    __shared__ __half Kt[64][72];   // [m][d]
    __shared__ __half Vs[64][72];   // [m][d]
    __shared__ __half Ps[64][72];   // [n][m-chunk]
    __shared__ float sums[4][64];

    int tid = threadIdx.x, lane = tid & 31, wid = tid >> 5;
    int g = lane >> 2, j = lane & 3;
    int wm32 = (wid >> 2) * 32;
    int wn16 = (wid & 3) * 16;

    sums[tid >> 6][tid & 63] = 0.0f;

    for (int i = tid; i < 512; i += 256) {
        int r = i >> 3, seg = (i & 7) * 8;
        *(uint4*)&Qs[r][seg] =
            *(const uint4*)(qh + ((size_t)(b * 1024 + n0 + r) * 1024) + h * 64 + seg);
    }

    // V B-frag ldmatrix base (n-dim = d, warp covers wn16 .. wn16+15)
    int lmat = lane >> 3, lrow = lane & 7;
    uint32_t vFrag = smem_u32(&Vs[(lmat & 1) * 8 + lrow][wn16 + (lmat >> 1) * 8]);

    float o[2][2][4];
    #pragma unroll
    for (int mt = 0; mt < 2; mt++)
        #pragma unroll
        for (int nt = 0; nt < 2; nt++)
            #pragma unroll
            for (int r = 0; r < 4; r++) o[mt][nt][r] = 0.0f;

    for (int m0 = 0; m0 < 1024; m0 += 64) {
        __syncthreads();
        for (int i = tid; i < 512; i += 256) {
            int r = i >> 3, seg = (i & 7) * 8;
            const __half* kb = kvh + ((size_t)(b * 1024 + m0 + r) * 2048) + h * 64 + seg;
            *(uint4*)&Kt[r][seg] = *(const uint4*)kb;
            *(uint4*)&Vs[r][seg] = *(const uint4*)(kb + 1024);
        }
        __syncthreads();

        // S-mma: A = Qs, B = Kt (k-contiguous fp16 pairs -> LDS.32)
        float c[2][2][4];
        #pragma unroll
        for (int mt = 0; mt < 2; mt++)
            #pragma unroll
            for (int nt = 0; nt < 2; nt++)
                #pragma unroll
                for (int r = 0; r < 4; r++) c[mt][nt][r] = 0.0f;

        #pragma unroll
        for (int kk = 0; kk < 64; kk += 16) {
            uint32_t a[2][4], bf[2][2];
            #pragma unroll
            for (int mt = 0; mt < 2; mt++) {
                const __half* p0 = &Qs[wm32 + mt * 16 + g][kk + 2 * j];
                a[mt][0] = *(const uint32_t*)p0;
                a[mt][1] = *(const uint32_t*)(p0 + 8 * 72);
                a[mt][2] = *(const uint32_t*)(p0 + 8);
                a[mt][3] = *(const uint32_t*)(p0 + 8 * 72 + 8);
            }
            #pragma unroll
            for (int nt = 0; nt < 2; nt++) {
                const __half* p0 = &Kt[wn16 + nt * 8 + g][kk + 2 * j];
                bf[nt][0] = *(const uint32_t*)p0;
                bf[nt][1] = *(const uint32_t*)(p0 + 8);
            }
            #pragma unroll
            for (int mt = 0; mt < 2; mt++)
                #pragma unroll
                for (int nt = 0; nt < 2; nt++)
                    MMA_F16(c[mt][nt][0], c[mt][nt][1], c[mt][nt][2], c[mt][nt][3],
                            a[mt][0], a[mt][1], a[mt][2], a[mt][3],
                            bf[nt][0], bf[nt][1]);
        }

        // E = exp(0.125*S) -> fp16 (tmp, Ps); row sums of the fp16 values
        #pragma unroll
        for (int mt = 0; mt < 2; mt++) {
            int r1 = wm32 + mt * 16 + g;
            float eA = 0.0f, eB = 0.0f;
            #pragma unroll
            for (int nt = 0; nt < 2; nt++) {
                int col = wn16 + nt * 8 + 2 * j;
                float e0 = __expf(0.125f * c[mt][nt][0]);
                float e1 = __expf(0.125f * c[mt][nt][1]);
                float e2 = __expf(0.125f * c[mt][nt][2]);
                float e3 = __expf(0.125f * c[mt][nt][3]);
                __half2 h01 = __floats2half2_rn(e0, e1);
                __half2 h23 = __floats2half2_rn(e2, e3);
                size_t idx = ((size_t)bh * 1024 + n0 + r1) * 1024 + m0 + col;
                __stcs((unsigned int*)(tmp + idx),            *(uint32_t*)&h01);
                __stcs((unsigned int*)(tmp + idx + 8 * 1024), *(uint32_t*)&h23);
                *(uint32_t*)&Ps[r1][col]     = *(uint32_t*)&h01;
                *(uint32_t*)&Ps[r1 + 8][col] = *(uint32_t*)&h23;
                float2 f01 = __half22float2(h01);
                float2 f23 = __half22float2(h23);
                eA += f01.x + f01.y;
                eB += f23.x + f23.y;
            }
            eA += __shfl_xor_sync(0xffffffffu, eA, 1);
            eA += __shfl_xor_sync(0xffffffffu, eA, 2);
            eB += __shfl_xor_sync(0xffffffffu, eB, 1);
            eB += __shfl_xor_sync(0xffffffffu, eB, 2);
            if (j == 0) {
                sums[wn16 >> 4][r1]     += eA;
                sums[wn16 >> 4][r1 + 8] += eB;
            }
        }
        __syncthreads();

        // PV-mma: A = Ps (LDS.32 pairs), B = Vs (ldmatrix.trans)
        #pragma unroll
        for (int kk = 0; kk < 64; kk += 16) {
            uint32_t a[2][4], bf[2][2];
            #pragma unroll
            for (int mt = 0; mt < 2; mt++) {
                const __half* p0 = &Ps[wm32 + mt * 16 + g][kk + 2 * j];
                a[mt][0] = *(const uint32_t*)p0;
                a[mt][1] = *(const uint32_t*)(p0 + 8 * 72);
                a[mt][2] = *(const uint32_t*)(p0 + 8);
                a[mt][3] = *(const uint32_t*)(p0 + 8 * 72 + 8);
            }
            LDSM_X4_T(bf[0][0], bf[0][1], bf[1][0], bf[1][1],
                      vFrag + kk * 144);
            #pragma unroll
            for (int mt = 0; mt < 2; mt++)
                #pragma unroll
                for (int nt = 0; nt < 2; nt++)
                    MMA_F16(o[mt][nt][0], o[mt][nt][1], o[mt][nt][2], o[mt][nt][3],
                            a[mt][0], a[mt][1], a[mt][2], a[mt][3],
                            bf[nt][0], bf[nt][1]);
        }
    }

    __syncthreads();
    if (tid < 64) {
        float tot = sums[0][tid] + sums[1][tid] + sums[2][tid] + sums[3][tid];
        float r = 1.0f / tot;
        sums[0][tid] = r;
        rowrl[(size_t)bh * 1024 + n0 + tid] = r;
    }
    __syncthreads();

    #pragma unroll
    for (int mt = 0; mt < 2; mt++) {
        int r1 = wm32 + mt * 16 + g;
        float rlA = sums[0][r1], rlB = sums[0][r1 + 8];
        #pragma unroll
        for (int nt = 0; nt < 2; nt++) {
            int col = wn16 + nt * 8 + 2 * j;
            __half* base = attouth + ((size_t)(b * 1024 + n0 + r1) * 1024) + h * 64 + col;
            __half2 h01 = __floats2half2_rn(o[mt][nt][0] * rlA, o[mt][nt][1] * rlA);
            __half2 h23 = __floats2half2_rn(o[mt][nt][2] * rlB, o[mt][nt][3] * rlB);
            *(uint32_t*)base              = *(uint32_t*)&h01;
            *(uint32_t*)(base + 8 * 1024) = *(uint32_t*)&h23;
        }
    }
}

// ---------------------------------------------------------------------------
// Normalize + transpose: out(b,n,m,h) = E_fp16(b,h,n,m) * rl(b,h,n).
// Block per (b,n); 4 m-chunks of 256. uint4 loads (8 halves) for MLP depth.
// ---------------------------------------------------------------------------
__global__ void attn_tr(const __half* __restrict__ tmp, const float* __restrict__ rowrl,
                        float* __restrict__ outAttn)
{
    int b = blockIdx.y;
    int n = blockIdx.x;
    __shared__ float T[16][257];
    __shared__ float rl_s[16];
    int tid = threadIdx.x;
    if (tid < 16) rl_s[tid] = rowrl[(size_t)(b * 16 + tid) * 1024 + n];
    __syncthreads();

    for (int m0 = 0; m0 < 1024; m0 += 256) {
        // 16 heads x 256 m = 4096 halves = 512 uint4 loads; 2 per thread
        for (int i = tid; i < 512; i += 256) {
            int hh = i & 15;
            int mm = (i >> 4) * 8;
            uint4 raw = __ldcs((const uint4*)
                (tmp + ((size_t)(b * 16 + hh) * 1024 + n) * 1024 + m0 + mm));
            float rl = rl_s[hh];
            __half2 v0 = *(__half2*)&raw.x;
            __half2 v1 = *(__half2*)&raw.y;
            __half2 v2 = *(__half2*)&raw.z;
            __half2 v3 = *(__half2*)&raw.w;
            float2 f0 = __half22float2(v0);
            float2 f1 = __half22float2(v1);
            float2 f2 = __half22float2(v2);
            float2 f3 = __half22float2(v3);
            float* tr = &T[hh][mm];
            tr[0] = f0.x * rl; tr[1] = f0.y * rl;
            tr[2] = f1.x * rl; tr[3] = f1.y * rl;
            tr[4] = f2.x * rl; tr[5] = f2.y * rl;
            tr[6] = f3.x * rl; tr[7] = f3.y * rl;
        }
        __syncthreads();
        float* dst = outAttn + ((size_t)(b * 1024 + n) * 1024 + m0 + tid) * 16;
        #pragma unroll
        for (int k = 0; k < 16; k += 4) {
            __stcs((float4*)(dst + k),
                   make_float4(T[k][tid], T[k + 1][tid], T[k + 2][tid], T[k + 3][tid]));
        }
        __syncthreads();
    }
}

// ---------------------------------------------------------------------------
// Row softmax over contiguous 1024 (combine weights), fp16 out.
// ---------------------------------------------------------------------------
__global__ void row_softmax(const float* __restrict__ in, __half* __restrict__ outp)
{
    size_t row = blockIdx.x;
    const float4* L = (const float4*)(in + row * 1024);
    int t = threadIdx.x;
    float4 v = L[t];
    float mx = fmaxf(fmaxf(v.x, v.y), fmaxf(v.z, v.w));
    __shared__ float smA[8], smB[8];
    #pragma unroll
    for (int off = 16; off; off >>= 1) mx = fmaxf(mx, __shfl_xor_sync(0xffffffffu, mx, off));
    if ((t & 31) == 0) smA[t >> 5] = mx;
    __syncthreads();
    mx = smA[0];
    #pragma unroll
    for (int w = 1; w < 8; w++) mx = fmaxf(mx, smA[w]);
    float e0 = __expf(v.x - mx), e1 = __expf(v.y - mx);
    float e2 = __expf(v.z - mx), e3 = __expf(v.w - mx);
    float s = e0 + e1 + e2 + e3;
    #pragma unroll
    for (int off = 16; off; off >>= 1) s += __shfl_xor_sync(0xffffffffu, s, off);
    if ((t & 31) == 0) smB[t >> 5] = s;
    __syncthreads();
    s = 0.0f;
    #pragma unroll
    for (int w = 0; w < 8; w++) s += smB[w];
    float r = 1.0f / s;
    __half2 h01 = __floats2half2_rn(e0 * r, e1 * r);
    __half2 h23 = __floats2half2_rn(e2 * r, e3 * r);
    uint2 o;
    o.x = *(uint32_t*)&h01;
    o.y = *(uint32_t*)&h23;
    ((uint2*)(outp + row * 1024))[t] = o;
}

// ---------------------------------------------------------------------------
// Dispatch softmax over token axis n, written TRANSPOSED, fp16 out.
// ---------------------------------------------------------------------------
__global__ void disp_softmax(const float* __restrict__ logits, __half* __restrict__ dispT)
{
    int b = blockIdx.y;
    int c0 = blockIdx.x * 64;
    const float* L = logits + (size_t)b * 1048576;
    __half* O = dispT + (size_t)b * 1048576;
    int tid = threadIdx.x;
    int tx = tid & 63, ty = tid >> 6;   // 4 x 64
    int col = c0 + tx;

    __shared__ float red[4][64];
    float mx = -1e30f;
    for (int n = ty; n < 1024; n += 4) mx = fmaxf(mx, L[(size_t)n * 1024 + col]);
    red[ty][tx] = mx;
    __syncthreads();
    mx = fmaxf(fmaxf(red[0][tx], red[1][tx]), fmaxf(red[2][tx], red[3][tx]));
    __syncthreads();
    float s = 0.0f;
    for (int n = ty; n < 1024; n += 4) s += __expf(L[(size_t)n * 1024 + col] - mx);
    red[ty][tx] = s;
    __syncthreads();
    s = red[0][tx] + red[1][tx] + red[2][tx] + red[3][tx];
    float rinv = 1.0f / s;
    __syncthreads();

    __shared__ float T[64][65];
    for (int n0 = 0; n0 < 1024; n0 += 64) {
        for (int n = ty; n < 64; n += 4)
            T[tx][n] = __expf(L[(size_t)(n0 + n) * 1024 + col] - mx) * rinv;
        __syncthreads();
        int cl = tid >> 2;
        int nl = (tid & 3) * 16;
        __half* dst = O + (size_t)(c0 + cl) * 1024 + n0 + nl;
        #pragma unroll
        for (int k = 0; k < 16; k += 4) {
            __half2 h01 = __floats2half2_rn(T[cl][nl + k],     T[cl][nl + k + 1]);
            __half2 h23 = __floats2half2_rn(T[cl][nl + k + 2], T[cl][nl + k + 3]);
            uint2 o;
            o.x = *(uint32_t*)&h01;
            o.y = *(uint32_t*)&h23;
            *(uint2*)(dst + k) = o;
        }
        __syncthreads();
    }
}

// ---------------------------------------------------------------------------
// Fused residual + LayerNorm: out = LN(a + coefb * bsrc) * g + beta.
// If outH != null: values RNE-rounded to fp16, written to BOTH outp (f32)
// and outH (fp16) so GEMM inputs == residual values exactly.
// ---------------------------------------------------------------------------
__global__ void ln_res(const float* __restrict__ a, const float* __restrict__ bsrc,
                       float coefb, const float* __restrict__ g,
                       const float* __restrict__ beta, float* __restrict__ outp,
                       __half* __restrict__ outH)
{
    size_t row = blockIdx.x;
    int t = threadIdx.x;
    float4 av = ((const float4*)(a + row * 1024))[t];
    float4 bv = ((const float4*)(bsrc + row * 1024))[t];
    float x0 = av.x + coefb * bv.x;
    float x1 = av.y + coefb * bv.y;
    float x2 = av.z + coefb * bv.z;
    float x3 = av.w + coefb * bv.w;
    float s = x0 + x1 + x2 + x3;
    float q = x0 * x0 + x1 * x1 + x2 * x2 + x3 * x3;
    __shared__ float smA[8], smB[8];
    #pragma unroll
    for (int off = 16; off; off >>= 1) {
        s += __shfl_xor_sync(0xffffffffu, s, off);
        q += __shfl_xor_sync(0xffffffffu, q, off);
    }
    if ((t & 31) == 0) { smA[t >> 5] = s; smB[t >> 5] = q; }
    __syncthreads();
    s = 0.0f; q = 0.0f;
    #pragma unroll
    for (int w = 0; w < 8; w++) { s += smA[w]; q += smB[w]; }
    float mu = s * (1.0f / 1024.0f);
    float var = q * (1.0f / 1024.0f) - mu * mu;
    float rs = rsqrtf(var + 1e-5f);
    float4 gv = ((const float4*)g)[t];
    float4 btv = ((const float4*)beta)[t];
    float4 out4;
    out4.x = (x0 - mu) * rs * gv.x + btv.x;
    out4.y = (x1 - mu) * rs * gv.y + btv.y;
    out4.z = (x2 - mu) * rs * gv.z + btv.z;
    out4.w = (x3 - mu) * rs * gv.w + btv.w;
    if (outH) {
        __half2 h01 = __floats2half2_rn(out4.x, out4.y);
        __half2 h23 = __floats2half2_rn(out4.z, out4.w);
        uint2 o;
        o.x = *(uint32_t*)&h01;
        o.y = *(uint32_t*)&h23;
        ((uint2*)(outH + row * 1024))[t] = o;
        float2 f01 = __half22float2(h01);
        float2 f23 = __half22float2(h23);
        out4.x = f01.x; out4.y = f01.y; out4.z = f23.x; out4.w = f23.y;
    }
    ((float4*)(outp + row * 1024))[t] = out4;
}

// ---------------------------------------------------------------------------
// Launcher
// ---------------------------------------------------------------------------
extern "C" void kernel_launch(void* const* d_in, const int* in_sizes, int n_in,
                              void* d_out, int out_size)
{
    const float* x   = (const float*)d_in[0];
    const float* Wq  = (const float*)d_in[1];
    const float* bq  = (const float*)d_in[2];
    const float* Wkv = (const float*)d_in[3];
    const float* bkv = (const float*)d_in[4];
    const float* Wp  = (const float*)d_in[5];
    const float* bp  = (const float*)d_in[6];
    const float* g1  = (const float*)d_in[7];
    const float* b1  = (const float*)d_in[8];
    const float* phi = (const float*)d_in[9];
    const float* We1 = (const float*)d_in[10];
    const float* be1 = (const float*)d_in[11];
    const float* We2 = (const float*)d_in[12];
    const float* be2 = (const float*)d_in[13];
    const float* g2  = (const float*)d_in[14];
    const float* b2  = (const float*)d_in[15];

    float* arena = nullptr;
    cudaGetSymbolAddress((void**)&arena, g_arena);

    __half* tmp     = (__half*)(arena + OFF_TMP);
    float*  proj    = arena + OFF_PROJ;
    float*  x1      = arena + OFF_X1;
    float*  logits  = arena + OFF_LOGITS;
    float*  moeout  = arena + OFF_MOE;
    float*  rl      = arena + OFF_RL;
    __half* xh      = (__half*)(arena + OFF_XH);
    __half* Wqh     = (__half*)(arena + OFF_WQH);
    __half* Wkvh    = (__half*)(arena + OFF_WKVH);
    __half* Wph     = (__half*)(arena + OFF_WPH);
    __half* phih    = (__half*)(arena + OFF_PHIH);
    __half* We1h    = (__half*)(arena + OFF_WE1H);
    __half* We2h    = (__half*)(arena + OFF_WE2H);
    __half* qh      = (__half*)(arena + OFF_QH);
    __half* kvh     = (__half*)(arena + OFF_KVH);
    __half* attouth = (__half*)(arena + OFF_ATTOUTH);
    __half* x1h     = (__half*)(arena + OFF_X1H);
    __half* dispTh  = (__half*)(arena + OFF_DISPTH);
    __half* combh   = (__half*)(arena + OFF_COMBH);
    __half* slotsh  = (__half*)(arena + OFF_SLOTSH);
    __half* hh      = (__half*)(arena + OFF_HH);
    __half* ymoeh   = (__half*)(arena + OFF_YMOEH);

    float* out = (float*)d_out;
    float* outAttn = out + 4194304;

    dim3 T(256);

    // prep: RNE-round all GEMM inputs to fp16, one launch (6553600 float4 groups)
    round_all<<<25600, T>>>(x, Wq, Wkv, Wp, phi, We1, We2,
                            xh, Wqh, Wkvh, Wph, phih, We1h, We2h);

    // q = x @ Wq + bq          (4096x1024x1024) -> fp16
    hgemm<<<dim3(8, 32, 1), T>>>(xh, Wqh, bq, nullptr, qh, 4096, 1024, 1024,
                                 0, 0, 0, 0, 1, 1);
    // kv = x @ Wkv + bkv       (4096x2048x1024) -> fp16
    hgemm<<<dim3(16, 32, 1), T>>>(xh, Wkvh, bkv, nullptr, kvh, 4096, 2048, 1024,
                                  0, 0, 0, 0, 1, 1);

    // fused attention + transpose
    att_fused<<<dim3(16, 64), T>>>(qh, kvh, tmp, rl, attouth);
    attn_tr<<<dim3(1024, 4), T>>>(tmp, rl, outAttn);

    // out-proj (f32) + residual LN (x1 f32 + fp16)
    hgemm<<<dim3(8, 32, 1), T>>>(attouth, Wph, bp, proj, nullptr, 4096, 1024, 1024,
                                 0, 0, 0, 0, 1, 1);
    ln_res<<<4096, T>>>(proj, x, 1.0f, g1, b1, x1, x1h);

    // soft-MoE
    hgemm<<<dim3(8, 32, 1), T>>>(x1h, phih, nullptr, logits, nullptr, 4096, 1024, 1024,
                                 0, 0, 0, 0, 1, 0);
    row_softmax<<<4096, T>>>(logits, combh);
    disp_softmax<<<dim3(16, 4), T>>>(logits, dispTh);

    // slots[b] = dispT[b] @ x1[b] -> fp16
    hgemm<<<dim3(8, 8, 4), T>>>(dispTh, x1h, nullptr, nullptr, slotsh, 1024, 1024, 1024,
                                1048576, 1048576, 0, 1048576, 0, 0);
    // h = gelu(slots @ We1[e] + be1[e]) -> fp16
    hgemm<<<dim3(32, 4, 8), T>>>(slotsh, We1h, be1, nullptr, hh, 512, 4096, 1024,
                                 524288, 4194304, 4096, 2097152, 2, 2);
    // y = h @ We2[e] + be2[e] -> fp16
    hgemm<<<dim3(8, 4, 8), T>>>(hh, We2h, be2, nullptr, ymoeh, 512, 1024, 4096,
                                2097152, 4194304, 1024, 524288, 2, 1);
    // moe_out[b] = comb[b] @ ymoe[b] -> f32
    hgemm<<<dim3(8, 8, 4), T>>>(combh, ymoeh, nullptr, moeout, nullptr, 1024, 1024, 1024,
                                1048576, 1048576, 0, 1048576, 0, 0);

    // y = LN(moe_out + 2*x1)
    ln_res<<<4096, T>>>(moeout, x1, 2.0f, g2, b2, out, nullptr);
}

// round 13
// speedup vs baseline: 1.9593x; 1.0067x over previous
#include <cuda_runtime.h>
#include <cuda_fp16.h>
#include <math.h>
#include <stdint.h>

// ---------------------------------------------------------------------------
// Problem constants
//   B=4, SEQ=1024, DIM=1024, HEADS=16, N_EXP=2, SLOTS=512, HID=4096
// Output: [ y : 4*1024*1024 f32 ][ attn : 4*1024*1024*16 f32 ]
// All GEMM/attention operands fp16 (RNE-rounded at producer), fp32 accumulate.
// ---------------------------------------------------------------------------

// arena offsets in FLOAT units (fp16 buffers occupy elem_count/2 float slots)
#define OFF_TMP      0LL           // 64M halves = 32M floats
#define OFF_PROJ     33554432LL    // 4M f32
#define OFF_X1       37748736LL    // 4M f32
#define OFF_LOGITS   41943040LL    // 4M f32
#define OFF_MOE      46137344LL    // 4M f32
#define OFF_RL       50331648LL    // 64K f32
#define OFF_XH       50397184LL    // 4M halves
#define OFF_WQH      52494336LL    // 1M halves
#define OFF_WKVH     53018624LL    // 2M halves
#define OFF_WPH      54067200LL    // 1M halves
#define OFF_PHIH     54591488LL    // 1M halves
#define OFF_WE1H     55115776LL    // 8M halves
#define OFF_WE2H     59310080LL    // 8M halves
#define OFF_QH       63504384LL    // 4M halves
#define OFF_KVH      65601536LL    // 8M halves
#define OFF_ATTOUTH  69795840LL    // 4M halves
#define OFF_X1H      71892992LL    // 4M halves
#define OFF_DISPTH   73990144LL    // 4M halves
#define OFF_COMBH    76087296LL    // 4M halves
#define OFF_SLOTSH   78184448LL    // 4M halves (4 batches x 1024x1024)
#define OFF_HH       80281600LL    // 16M halves (8 batches x 512x4096)
#define OFF_YMOEH    88670208LL    // 4M halves (8 batches x 512x1024)
#define ARENA_FLOATS 90767360LL

__device__ float g_arena[ARENA_FLOATS];

__device__ __forceinline__ float gelu_tanh(float v) {
    const float c0 = 0.7978845608028654f;   // sqrt(2/pi)
    float t = tanhf(c0 * (v + 0.044715f * v * v * v));
    return 0.5f * v * (1.0f + t);
}

__device__ __forceinline__ uint32_t smem_u32(const void* p) {
    return (uint32_t)__cvta_generic_to_shared(p);
}

#define CP16(dst, src) \
    asm volatile("cp.async.cg.shared.global [%0], [%1], 16;" :: "r"(dst), "l"(src))
#define CP_COMMIT() asm volatile("cp.async.commit_group;")
#define CP_WAIT0()  asm volatile("cp.async.wait_group 0;")

#define MMA_F16(c0,c1,c2,c3,a0,a1,a2,a3,b0,b1)                                \
    asm volatile("mma.sync.aligned.m16n8k16.row.col.f32.f16.f16.f32 "         \
                 "{%0,%1,%2,%3},{%4,%5,%6,%7},{%8,%9},{%0,%1,%2,%3};"         \
                 : "+f"(c0), "+f"(c1), "+f"(c2), "+f"(c3)                     \
                 : "r"(a0), "r"(a1), "r"(a2), "r"(a3), "r"(b0), "r"(b1))

#define LDSM_X4(r0,r1,r2,r3,addr)                                             \
    asm volatile("ldmatrix.sync.aligned.m8n8.x4.shared.b16 {%0,%1,%2,%3}, [%4];" \
                 : "=r"(r0), "=r"(r1), "=r"(r2), "=r"(r3) : "r"(addr))

#define LDSM_X4_T(r0,r1,r2,r3,addr)                                           \
    asm volatile("ldmatrix.sync.aligned.m8n8.x4.trans.shared.b16 {%0,%1,%2,%3}, [%4];" \
                 : "=r"(r0), "=r"(r1), "=r"(r2), "=r"(r3) : "r"(addr))

extern __shared__ __half dynh[];

// ---------------------------------------------------------------------------
// RNE-round all seven GEMM input buffers f32 -> fp16 in ONE launch.
// ---------------------------------------------------------------------------
__global__ void round_all(const float* __restrict__ x,  const float* __restrict__ Wq,
                          const float* __restrict__ Wkv,const float* __restrict__ Wp,
                          const float* __restrict__ phi,const float* __restrict__ We1,
                          const float* __restrict__ We2,
                          __half* __restrict__ xh,  __half* __restrict__ Wqh,
                          __half* __restrict__ Wkvh,__half* __restrict__ Wph,
                          __half* __restrict__ phih,__half* __restrict__ We1h,
                          __half* __restrict__ We2h)
{
    long long i = (long long)blockIdx.x * blockDim.x + threadIdx.x;
    const float* s; __half* d; long long off;
    if      (i < 1048576LL) { s = x;   d = xh;   off = i; }
    else if (i < 1310720LL) { s = Wq;  d = Wqh;  off = i - 1048576LL; }
    else if (i < 1835008LL) { s = Wkv; d = Wkvh; off = i - 1310720LL; }
    else if (i < 2097152LL) { s = Wp;  d = Wph;  off = i - 1835008LL; }
    else if (i < 2359296LL) { s = phi; d = phih; off = i - 2097152LL; }
    else if (i < 4456448LL) { s = We1; d = We1h; off = i - 2359296LL; }
    else if (i < 6553600LL) { s = We2; d = We2h; off = i - 4456448LL; }
    else return;
    float4 v = ((const float4*)s)[off];
    __half2 h01 = __floats2half2_rn(v.x, v.y);
    __half2 h23 = __floats2half2_rn(v.z, v.w);
    uint2 o;
    o.x = *(uint32_t*)&h01;
    o.y = *(uint32_t*)&h23;
    ((uint2*)d)[off] = o;
}

// ---------------------------------------------------------------------------
// fp16 tensor-core batched GEMM (m16n8k16, fp32 accum). (unchanged from R12)
// ---------------------------------------------------------------------------
__global__ void __launch_bounds__(256, 2)
hgemm(const __half* __restrict__ A, const __half* __restrict__ Bm,
      const float* __restrict__ bias, float* __restrict__ Cf,
      __half* __restrict__ Ch,
      int M, int N, int K,
      long long sA, long long sB, long long sBias, long long sC,
      int nBmod, int act)
{
    int z = blockIdx.z;
    int zb = nBmod ? (z % nBmod) : z;
    A  += (long long)z * sA;
    Bm += (long long)zb * sB;
    if (act >= 1) bias += (long long)zb * sBias;
    if (Cf) Cf += (long long)z * sC;
    if (Ch) Ch += (long long)z * sC;

    __shared__ __half As[2][128][40];   // [m][k32 pad 40]
    __shared__ __half Bs[2][32][136];   // [k][n128 pad 136]

    int bx = blockIdx.x, by = blockIdx.y;
    int tid = threadIdx.x;
    int wid = tid >> 5;
    int lane = tid & 31;
    int g = lane >> 2;
    int j = lane & 3;
    int wm64 = (wid >> 2) * 64;
    int wn32 = (wid & 3) * 32;

    int aRow = tid >> 1;
    int aKc  = (tid & 1) * 16;
    int bRow = tid >> 3;
    int bCc  = (tid & 7) * 16;

    const __half* Ap = A + (long long)(by * 128 + aRow) * K + aKc;
    const __half* Bp = Bm + (long long)bRow * N + bx * 128 + bCc;

    uint32_t aSm = smem_u32(&As[0][aRow][aKc]);
    uint32_t bSm = smem_u32(&Bs[0][bRow][bCc]);
    const uint32_t A_BUF = 128 * 40 * 2;
    const uint32_t B_BUF = 32 * 136 * 2;

    int lmat = lane >> 3, lrow = lane & 7;
    uint32_t aFrag[4];
    #pragma unroll
    for (int mt = 0; mt < 4; mt++)
        aFrag[mt] = smem_u32(
            &As[0][wm64 + mt * 16 + (lmat & 1) * 8 + lrow][(lmat >> 1) * 8]);
    uint32_t bFrag[2];
    #pragma unroll
    for (int p = 0; p < 2; p++)
        bFrag[p] = smem_u32(
            &Bs[0][(lmat & 1) * 8 + lrow][wn32 + p * 16 + (lmat >> 1) * 8]);

    float c[4][4][4];
    #pragma unroll
    for (int mt = 0; mt < 4; mt++)
        #pragma unroll
        for (int nt = 0; nt < 4; nt++)
            #pragma unroll
            for (int r = 0; r < 4; r++) c[mt][nt][r] = 0.0f;

    CP16(aSm, Ap);            CP16(aSm + 16, Ap + 8);
    CP16(bSm, Bp);            CP16(bSm + 16, Bp + 8);
    CP_COMMIT();

    int buf = 0;
    for (int k0 = 0; k0 < K; k0 += 32) {
        CP_WAIT0();
        __syncthreads();

        if (k0 + 32 < K) {
            Ap += 32;
            Bp += (long long)32 * N;
            uint32_t aD = aSm + (buf ^ 1) * A_BUF;
            uint32_t bD = bSm + (buf ^ 1) * B_BUF;
            CP16(aD, Ap);        CP16(aD + 16, Ap + 8);
            CP16(bD, Bp);        CP16(bD + 16, Bp + 8);
            CP_COMMIT();
        }

        uint32_t aB = (uint32_t)buf * A_BUF;
        uint32_t bB = (uint32_t)buf * B_BUF;

        #pragma unroll
        for (int kk = 0; kk < 32; kk += 16) {
            uint32_t a[4][4];
            uint32_t bfr[4][2];
            #pragma unroll
            for (int mt = 0; mt < 4; mt++)
                LDSM_X4(a[mt][0], a[mt][1], a[mt][2], a[mt][3],
                        aFrag[mt] + aB + kk * 2);
            #pragma unroll
            for (int p = 0; p < 2; p++)
                LDSM_X4_T(bfr[2 * p][0], bfr[2 * p][1],
                          bfr[2 * p + 1][0], bfr[2 * p + 1][1],
                          bFrag[p] + bB + kk * 272);
            #pragma unroll
            for (int mt = 0; mt < 4; mt++)
                #pragma unroll
                for (int nt = 0; nt < 4; nt++)
                    MMA_F16(c[mt][nt][0], c[mt][nt][1], c[mt][nt][2], c[mt][nt][3],
                            a[mt][0], a[mt][1], a[mt][2], a[mt][3],
                            bfr[nt][0], bfr[nt][1]);
        }
        buf ^= 1;
    }

    #pragma unroll
    for (int mt = 0; mt < 4; mt++) {
        int r0 = by * 128 + wm64 + mt * 16 + g;
        #pragma unroll
        for (int nt = 0; nt < 4; nt++) {
            int col = bx * 128 + wn32 + nt * 8 + 2 * j;
            float b0 = 0.0f, b1 = 0.0f;
            if (act >= 1) { b0 = bias[col]; b1 = bias[col + 1]; }
            float v0 = c[mt][nt][0] + b0;
            float v1 = c[mt][nt][1] + b1;
            float v2 = c[mt][nt][2] + b0;
            float v3 = c[mt][nt][3] + b1;
            if (act == 2) {
                v0 = gelu_tanh(v0); v1 = gelu_tanh(v1);
                v2 = gelu_tanh(v2); v3 = gelu_tanh(v3);
            }
            if (Cf) {
                *(float2*)(Cf + (long long)r0 * N + col)       = make_float2(v0, v1);
                *(float2*)(Cf + (long long)(r0 + 8) * N + col) = make_float2(v2, v3);
            }
            if (Ch) {
                __half2 h01 = __floats2half2_rn(v0, v1);
                __half2 h23 = __floats2half2_rn(v2, v3);
                *(uint32_t*)(Ch + (long long)r0 * N + col)       = *(uint32_t*)&h01;
                *(uint32_t*)(Ch + (long long)(r0 + 8) * N + col) = *(uint32_t*)&h23;
            }
        }
    }
}

// ---------------------------------------------------------------------------
// Fused attention (fp16 HMMA): per (b,h), n-tile 128.
// 8 warps = 4(n) x 2(m); warp tile 32n x 32m. S = Q K^T; E = exp(0.125*S)
// -> tmp fp16 + smem Ps; O = (E@V)/rowsum -> attout fp16.
// Dynamic smem (56.3KB): Qs[128][72] Kt[64][72] Vs[64][72] Ps[128][72]
// + sums[2][128] f32. All rows 144B (16B-aligned); LDS.32 frags bank-clean.
// ---------------------------------------------------------------------------
__global__ void __launch_bounds__(256)
att_fused(const __half* __restrict__ qh, const __half* __restrict__ kvh,
          __half* __restrict__ tmp, float* __restrict__ rowrl,
          __half* __restrict__ attouth)
{
    int bh = blockIdx.y;
    int b = bh >> 4, h = bh & 15;
    int n0 = blockIdx.x * 128;

    __half* Qs = dynh;              // [128][72]
    __half* Kt = dynh + 9216;       // [64][72]
    __half* Vs = dynh + 13824;      // [64][72]
    __half* Ps = dynh + 18432;      // [128][72]
    float* sums = (float*)(dynh + 27648);   // [2][128]

    int tid = threadIdx.x, lane = tid & 31, wid = tid >> 5;
    int g = lane >> 2, j = lane & 3;
    int wn32  = (wid >> 1) * 32;    // warp's n-row base (0..96)
    int wmc32 = (wid & 1) * 32;     // warp's m-col / d-col base (0 or 32)

    sums[tid] = 0.0f;

    // load Q tile: 128 rows x 64 d = 1024 uint4
    for (int i = tid; i < 1024; i += 256) {
        int r = i >> 3, seg = (i & 7) * 8;
        *(uint4*)&Qs[r * 72 + seg] =
            *(const uint4*)(qh + ((size_t)(b * 1024 + n0 + r) * 1024) + h * 64 + seg);
    }

    // V B-frag ldmatrix bases (2 per warp: d-cols wmc32+0..15, +16..31)
    int lmat = lane >> 3, lrow = lane & 7;
    uint32_t vFrag0 = smem_u32(&Vs[((lmat & 1) * 8 + lrow) * 72 + wmc32 + (lmat >> 1) * 8]);
    uint32_t vFrag1 = vFrag0 + 32;   // +16 halves

    float o[2][4][4];
    #pragma unroll
    for (int mt = 0; mt < 2; mt++)
        #pragma unroll
        for (int nt = 0; nt < 4; nt++)
            #pragma unroll
            for (int r = 0; r < 4; r++) o[mt][nt][r] = 0.0f;

    for (int m0 = 0; m0 < 1024; m0 += 64) {
        __syncthreads();
        for (int i = tid; i < 512; i += 256) {
            int r = i >> 3, seg = (i & 7) * 8;
            const __half* kb = kvh + ((size_t)(b * 1024 + m0 + r) * 2048) + h * 64 + seg;
            *(uint4*)&Kt[r * 72 + seg] = *(const uint4*)kb;
            *(uint4*)&Vs[r * 72 + seg] = *(const uint4*)(kb + 1024);
        }
        __syncthreads();

        // S-mma: A = Qs (warp rows wn32..+31), B = Kt (warp cols wmc32..+31)
        float c[2][4][4];
        #pragma unroll
        for (int mt = 0; mt < 2; mt++)
            #pragma unroll
            for (int nt = 0; nt < 4; nt++)
                #pragma unroll
                for (int r = 0; r < 4; r++) c[mt][nt][r] = 0.0f;

        #pragma unroll
        for (int kk = 0; kk < 64; kk += 16) {
            uint32_t a[2][4], bf[4][2];
            #pragma unroll
            for (int mt = 0; mt < 2; mt++) {
                const __half* p0 = &Qs[(wn32 + mt * 16 + g) * 72 + kk + 2 * j];
                a[mt][0] = *(const uint32_t*)p0;
                a[mt][1] = *(const uint32_t*)(p0 + 8 * 72);
                a[mt][2] = *(const uint32_t*)(p0 + 8);
                a[mt][3] = *(const uint32_t*)(p0 + 8 * 72 + 8);
            }
            #pragma unroll
            for (int nt = 0; nt < 4; nt++) {
                const __half* p0 = &Kt[(wmc32 + nt * 8 + g) * 72 + kk + 2 * j];
                bf[nt][0] = *(const uint32_t*)p0;
                bf[nt][1] = *(const uint32_t*)(p0 + 8);
            }
            #pragma unroll
            for (int mt = 0; mt < 2; mt++)
                #pragma unroll
                for (int nt = 0; nt < 4; nt++)
                    MMA_F16(c[mt][nt][0], c[mt][nt][1], c[mt][nt][2], c[mt][nt][3],
                            a[mt][0], a[mt][1], a[mt][2], a[mt][3],
                            bf[nt][0], bf[nt][1]);
        }

        // E = exp(0.125*S) -> fp16 (tmp, Ps); row sums of fp16 values
        #pragma unroll
        for (int mt = 0; mt < 2; mt++) {
            int r1 = wn32 + mt * 16 + g;
            float eA = 0.0f, eB = 0.0f;
            #pragma unroll
            for (int nt = 0; nt < 4; nt++) {
                int col = wmc32 + nt * 8 + 2 * j;
                float e0 = __expf(0.125f * c[mt][nt][0]);
                float e1 = __expf(0.125f * c[mt][nt][1]);
                float e2 = __expf(0.125f * c[mt][nt][2]);
                float e3 = __expf(0.125f * c[mt][nt][3]);
                __half2 h01 = __floats2half2_rn(e0, e1);
                __half2 h23 = __floats2half2_rn(e2, e3);
                size_t idx = ((size_t)bh * 1024 + n0 + r1) * 1024 + m0 + col;
                __stcs((unsigned int*)(tmp + idx),            *(uint32_t*)&h01);
                __stcs((unsigned int*)(tmp + idx + 8 * 1024), *(uint32_t*)&h23);
                *(uint32_t*)&Ps[r1 * 72 + col]       = *(uint32_t*)&h01;
                *(uint32_t*)&Ps[(r1 + 8) * 72 + col] = *(uint32_t*)&h23;
                float2 f01 = __half22float2(h01);
                float2 f23 = __half22float2(h23);
                eA += f01.x + f01.y;
                eB += f23.x + f23.y;
            }
            eA += __shfl_xor_sync(0xffffffffu, eA, 1);
            eA += __shfl_xor_sync(0xffffffffu, eA, 2);
            eB += __shfl_xor_sync(0xffffffffu, eB, 1);
            eB += __shfl_xor_sync(0xffffffffu, eB, 2);
            if (j == 0) {
                sums[(wid & 1) * 128 + r1]     += eA;
                sums[(wid & 1) * 128 + r1 + 8] += eB;
            }
        }
        __syncthreads();

        // PV-mma: A = Ps (warp rows), B = Vs (ldmatrix.trans, d cols wmc32..+31)
        #pragma unroll
        for (int kk = 0; kk < 64; kk += 16) {
            uint32_t a[2][4], bf[4][2];
            #pragma unroll
            for (int mt = 0; mt < 2; mt++) {
                const __half* p0 = &Ps[(wn32 + mt * 16 + g) * 72 + kk + 2 * j];
                a[mt][0] = *(const uint32_t*)p0;
                a[mt][1] = *(const uint32_t*)(p0 + 8 * 72);
                a[mt][2] = *(const uint32_t*)(p0 + 8);
                a[mt][3] = *(const uint32_t*)(p0 + 8 * 72 + 8);
            }
            LDSM_X4_T(bf[0][0], bf[0][1], bf[1][0], bf[1][1], vFrag0 + kk * 144);
            LDSM_X4_T(bf[2][0], bf[2][1], bf[3][0], bf[3][1], vFrag1 + kk * 144);
            #pragma unroll
            for (int mt = 0; mt < 2; mt++)
                #pragma unroll
                for (int nt = 0; nt < 4; nt++)
                    MMA_F16(o[mt][nt][0], o[mt][nt][1], o[mt][nt][2], o[mt][nt][3],
                            a[mt][0], a[mt][1], a[mt][2], a[mt][3],
                            bf[nt][0], bf[nt][1]);
        }
    }

    __syncthreads();
    if (tid < 128) {
        float tot = sums[tid] + sums[128 + tid];
        float r = 1.0f / tot;
        sums[tid] = r;
        rowrl[(size_t)bh * 1024 + n0 + tid] = r;
    }
    __syncthreads();

    #pragma unroll
    for (int mt = 0; mt < 2; mt++) {
        int r1 = wn32 + mt * 16 + g;
        float rlA = sums[r1], rlB = sums[r1 + 8];
        #pragma unroll
        for (int nt = 0; nt < 4; nt++) {
            int col = wmc32 + nt * 8 + 2 * j;
            __half* base = attouth + ((size_t)(b * 1024 + n0 + r1) * 1024) + h * 64 + col;
            __half2 h01 = __floats2half2_rn(o[mt][nt][0] * rlA, o[mt][nt][1] * rlA);
            __half2 h23 = __floats2half2_rn(o[mt][nt][2] * rlB, o[mt][nt][3] * rlB);
            *(uint32_t*)base              = *(uint32_t*)&h01;
            *(uint32_t*)(base + 8 * 1024) = *(uint32_t*)&h23;
        }
    }
}

// ---------------------------------------------------------------------------
// Normalize + transpose: out(b,n,m,h) = E_fp16(b,h,n,m) * rl(b,h,n).
// ---------------------------------------------------------------------------
__global__ void attn_tr(const __half* __restrict__ tmp, const float* __restrict__ rowrl,
                        float* __restrict__ outAttn)
{
    int b = blockIdx.y;
    int n = blockIdx.x;
    __shared__ float T[16][257];
    __shared__ float rl_s[16];
    int tid = threadIdx.x;
    if (tid < 16) rl_s[tid] = rowrl[(size_t)(b * 16 + tid) * 1024 + n];
    __syncthreads();

    for (int m0 = 0; m0 < 1024; m0 += 256) {
        for (int i = tid; i < 512; i += 256) {
            int hh = i & 15;
            int mm = (i >> 4) * 8;
            uint4 raw = __ldcs((const uint4*)
                (tmp + ((size_t)(b * 16 + hh) * 1024 + n) * 1024 + m0 + mm));
            float rl = rl_s[hh];
            __half2 v0 = *(__half2*)&raw.x;
            __half2 v1 = *(__half2*)&raw.y;
            __half2 v2 = *(__half2*)&raw.z;
            __half2 v3 = *(__half2*)&raw.w;
            float2 f0 = __half22float2(v0);
            float2 f1 = __half22float2(v1);
            float2 f2 = __half22float2(v2);
            float2 f3 = __half22float2(v3);
            float* tr = &T[hh][mm];
            tr[0] = f0.x * rl; tr[1] = f0.y * rl;
            tr[2] = f1.x * rl; tr[3] = f1.y * rl;
            tr[4] = f2.x * rl; tr[5] = f2.y * rl;
            tr[6] = f3.x * rl; tr[7] = f3.y * rl;
        }
        __syncthreads();
        float* dst = outAttn + ((size_t)(b * 1024 + n) * 1024 + m0 + tid) * 16;
        #pragma unroll
        for (int k = 0; k < 16; k += 4) {
            __stcs((float4*)(dst + k),
                   make_float4(T[k][tid], T[k + 1][tid], T[k + 2][tid], T[k + 3][tid]));
        }
        __syncthreads();
    }
}

// ---------------------------------------------------------------------------
// Row softmax over contiguous 1024 (combine weights), fp16 out.
// ---------------------------------------------------------------------------
__global__ void row_softmax(const float* __restrict__ in, __half* __restrict__ outp)
{
    size_t row = blockIdx.x;
    const float4* L = (const float4*)(in + row * 1024);
    int t = threadIdx.x;
    float4 v = L[t];
    float mx = fmaxf(fmaxf(v.x, v.y), fmaxf(v.z, v.w));
    __shared__ float smA[8], smB[8];
    #pragma unroll
    for (int off = 16; off; off >>= 1) mx = fmaxf(mx, __shfl_xor_sync(0xffffffffu, mx, off));
    if ((t & 31) == 0) smA[t >> 5] = mx;
    __syncthreads();
    mx = smA[0];
    #pragma unroll
    for (int w = 1; w < 8; w++) mx = fmaxf(mx, smA[w]);
    float e0 = __expf(v.x - mx), e1 = __expf(v.y - mx);
    float e2 = __expf(v.z - mx), e3 = __expf(v.w - mx);
    float s = e0 + e1 + e2 + e3;
    #pragma unroll
    for (int off = 16; off; off >>= 1) s += __shfl_xor_sync(0xffffffffu, s, off);
    if ((t & 31) == 0) smB[t >> 5] = s;
    __syncthreads();
    s = 0.0f;
    #pragma unroll
    for (int w = 0; w < 8; w++) s += smB[w];
    float r = 1.0f / s;
    __half2 h01 = __floats2half2_rn(e0 * r, e1 * r);
    __half2 h23 = __floats2half2_rn(e2 * r, e3 * r);
    uint2 o;
    o.x = *(uint32_t*)&h01;
    o.y = *(uint32_t*)&h23;
    ((uint2*)(outp + row * 1024))[t] = o;
}

// ---------------------------------------------------------------------------
// Dispatch softmax over token axis n, written TRANSPOSED, fp16 out.
// ---------------------------------------------------------------------------
__global__ void disp_softmax(const float* __restrict__ logits, __half* __restrict__ dispT)
{
    int b = blockIdx.y;
    int c0 = blockIdx.x * 64;
    const float* L = logits + (size_t)b * 1048576;
    __half* O = dispT + (size_t)b * 1048576;
    int tid = threadIdx.x;
    int tx = tid & 63, ty = tid >> 6;   // 4 x 64
    int col = c0 + tx;

    __shared__ float red[4][64];
    float mx = -1e30f;
    for (int n = ty; n < 1024; n += 4) mx = fmaxf(mx, L[(size_t)n * 1024 + col]);
    red[ty][tx] = mx;
    __syncthreads();
    mx = fmaxf(fmaxf(red[0][tx], red[1][tx]), fmaxf(red[2][tx], red[3][tx]));
    __syncthreads();
    float s = 0.0f;
    for (int n = ty; n < 1024; n += 4) s += __expf(L[(size_t)n * 1024 + col] - mx);
    red[ty][tx] = s;
    __syncthreads();
    s = red[0][tx] + red[1][tx] + red[2][tx] + red[3][tx];
    float rinv = 1.0f / s;
    __syncthreads();

    __shared__ float T[64][65];
    for (int n0 = 0; n0 < 1024; n0 += 64) {
        for (int n = ty; n < 64; n += 4)
            T[tx][n] = __expf(L[(size_t)(n0 + n) * 1024 + col] - mx) * rinv;
        __syncthreads();
        int cl = tid >> 2;
        int nl = (tid & 3) * 16;
        __half* dst = O + (size_t)(c0 + cl) * 1024 + n0 + nl;
        #pragma unroll
        for (int k = 0; k < 16; k += 4) {
            __half2 h01 = __floats2half2_rn(T[cl][nl + k],     T[cl][nl + k + 1]);
            __half2 h23 = __floats2half2_rn(T[cl][nl + k + 2], T[cl][nl + k + 3]);
            uint2 o;
            o.x = *(uint32_t*)&h01;
            o.y = *(uint32_t*)&h23;
            *(uint2*)(dst + k) = o;
        }
        __syncthreads();
    }
}

// ---------------------------------------------------------------------------
// Fused residual + LayerNorm: out = LN(a + coefb * bsrc) * g + beta.
// If outH != null: values RNE-rounded to fp16, written to BOTH outputs.
// ---------------------------------------------------------------------------
__global__ void ln_res(const float* __restrict__ a, const float* __restrict__ bsrc,
                       float coefb, const float* __restrict__ g,
                       const float* __restrict__ beta, float* __restrict__ outp,
                       __half* __restrict__ outH)
{
    size_t row = blockIdx.x;
    int t = threadIdx.x;
    float4 av = ((const float4*)(a + row * 1024))[t];
    float4 bv = ((const float4*)(bsrc + row * 1024))[t];
    float x0 = av.x + coefb * bv.x;
    float x1 = av.y + coefb * bv.y;
    float x2 = av.z + coefb * bv.z;
    float x3 = av.w + coefb * bv.w;
    float s = x0 + x1 + x2 + x3;
    float q = x0 * x0 + x1 * x1 + x2 * x2 + x3 * x3;
    __shared__ float smA[8], smB[8];
    #pragma unroll
    for (int off = 16; off; off >>= 1) {
        s += __shfl_xor_sync(0xffffffffu, s, off);
        q += __shfl_xor_sync(0xffffffffu, q, off);
    }
    if ((t & 31) == 0) { smA[t >> 5] = s; smB[t >> 5] = q; }
    __syncthreads();
    s = 0.0f; q = 0.0f;
    #pragma unroll
    for (int w = 0; w < 8; w++) { s += smA[w]; q += smB[w]; }
    float mu = s * (1.0f / 1024.0f);
    float var = q * (1.0f / 1024.0f) - mu * mu;
    float rs = rsqrtf(var + 1e-5f);
    float4 gv = ((const float4*)g)[t];
    float4 btv = ((const float4*)beta)[t];
    float4 out4;
    out4.x = (x0 - mu) * rs * gv.x + btv.x;
    out4.y = (x1 - mu) * rs * gv.y + btv.y;
    out4.z = (x2 - mu) * rs * gv.z + btv.z;
    out4.w = (x3 - mu) * rs * gv.w + btv.w;
    if (outH) {
        __half2 h01 = __floats2half2_rn(out4.x, out4.y);
        __half2 h23 = __floats2half2_rn(out4.z, out4.w);
        uint2 o;
        o.x = *(uint32_t*)&h01;
        o.y = *(uint32_t*)&h23;
        ((uint2*)(outH + row * 1024))[t] = o;
        float2 f01 = __half22float2(h01);
        float2 f23 = __half22float2(h23);
        out4.x = f01.x; out4.y = f01.y; out4.z = f23.x; out4.w = f23.y;
    }
    ((float4*)(outp + row * 1024))[t] = out4;
}

// ---------------------------------------------------------------------------
// Launcher
// ---------------------------------------------------------------------------
extern "C" void kernel_launch(void* const* d_in, const int* in_sizes, int n_in,
                              void* d_out, int out_size)
{
    const float* x   = (const float*)d_in[0];
    const float* Wq  = (const float*)d_in[1];
    const float* bq  = (const float*)d_in[2];
    const float* Wkv = (const float*)d_in[3];
    const float* bkv = (const float*)d_in[4];
    const float* Wp  = (const float*)d_in[5];
    const float* bp  = (const float*)d_in[6];
    const float* g1  = (const float*)d_in[7];
    const float* b1  = (const float*)d_in[8];
    const float* phi = (const float*)d_in[9];
    const float* We1 = (const float*)d_in[10];
    const float* be1 = (const float*)d_in[11];
    const float* We2 = (const float*)d_in[12];
    const float* be2 = (const float*)d_in[13];
    const float* g2  = (const float*)d_in[14];
    const float* b2  = (const float*)d_in[15];

    float* arena = nullptr;
    cudaGetSymbolAddress((void**)&arena, g_arena);

    __half* tmp     = (__half*)(arena + OFF_TMP);
    float*  proj    = arena + OFF_PROJ;
    float*  x1      = arena + OFF_X1;
    float*  logits  = arena + OFF_LOGITS;
    float*  moeout  = arena + OFF_MOE;
    float*  rl      = arena + OFF_RL;
    __half* xh      = (__half*)(arena + OFF_XH);
    __half* Wqh     = (__half*)(arena + OFF_WQH);
    __half* Wkvh    = (__half*)(arena + OFF_WKVH);
    __half* Wph     = (__half*)(arena + OFF_WPH);
    __half* phih    = (__half*)(arena + OFF_PHIH);
    __half* We1h    = (__half*)(arena + OFF_WE1H);
    __half* We2h    = (__half*)(arena + OFF_WE2H);
    __half* qh      = (__half*)(arena + OFF_QH);
    __half* kvh     = (__half*)(arena + OFF_KVH);
    __half* attouth = (__half*)(arena + OFF_ATTOUTH);
    __half* x1h     = (__half*)(arena + OFF_X1H);
    __half* dispTh  = (__half*)(arena + OFF_DISPTH);
    __half* combh   = (__half*)(arena + OFF_COMBH);
    __half* slotsh  = (__half*)(arena + OFF_SLOTSH);
    __half* hh      = (__half*)(arena + OFF_HH);
    __half* ymoeh   = (__half*)(arena + OFF_YMOEH);

    float* out = (float*)d_out;
    float* outAttn = out + 4194304;

    const int ATT_SMEM = 56320;   // (9216+4608+4608+9216)*2 + 256*4 bytes
    cudaFuncSetAttribute(att_fused, cudaFuncAttributeMaxDynamicSharedMemorySize, ATT_SMEM);

    dim3 T(256);

    // prep: RNE-round all GEMM inputs to fp16, one launch
    round_all<<<25600, T>>>(x, Wq, Wkv, Wp, phi, We1, We2,
                            xh, Wqh, Wkvh, Wph, phih, We1h, We2h);

    // q = x @ Wq + bq          (4096x1024x1024) -> fp16
    hgemm<<<dim3(8, 32, 1), T>>>(xh, Wqh, bq, nullptr, qh, 4096, 1024, 1024,
                                 0, 0, 0, 0, 1, 1);
    // kv = x @ Wkv + bkv       (4096x2048x1024) -> fp16
    hgemm<<<dim3(16, 32, 1), T>>>(xh, Wkvh, bkv, nullptr, kvh, 4096, 2048, 1024,
                                  0, 0, 0, 0, 1, 1);

    // fused attention (n-tile 128) + transpose
    att_fused<<<dim3(8, 64), T, ATT_SMEM>>>(qh, kvh, tmp, rl, attouth);
    attn_tr<<<dim3(1024, 4), T>>>(tmp, rl, outAttn);

    // out-proj (f32) + residual LN (x1 f32 + fp16)
    hgemm<<<dim3(8, 32, 1), T>>>(attouth, Wph, bp, proj, nullptr, 4096, 1024, 1024,
                                 0, 0, 0, 0, 1, 1);
    ln_res<<<4096, T>>>(proj, x, 1.0f, g1, b1, x1, x1h);

    // soft-MoE
    hgemm<<<dim3(8, 32, 1), T>>>(x1h, phih, nullptr, logits, nullptr, 4096, 1024, 1024,
                                 0, 0, 0, 0, 1, 0);
    row_softmax<<<4096, T>>>(logits, combh);
    disp_softmax<<<dim3(16, 4), T>>>(logits, dispTh);

    // slots[b] = dispT[b] @ x1[b] -> fp16
    hgemm<<<dim3(8, 8, 4), T>>>(dispTh, x1h, nullptr, nullptr, slotsh, 1024, 1024, 1024,
                                1048576, 1048576, 0, 1048576, 0, 0);
    // h = gelu(slots @ We1[e] + be1[e]) -> fp16
    hgemm<<<dim3(32, 4, 8), T>>>(slotsh, We1h, be1, nullptr, hh, 512, 4096, 1024,
                                 524288, 4194304, 4096, 2097152, 2, 2);
    // y = h @ We2[e] + be2[e] -> fp16
    hgemm<<<dim3(8, 4, 8), T>>>(hh, We2h, be2, nullptr, ymoeh, 512, 1024, 4096,
                                2097152, 4194304, 1024, 524288, 2, 1);
    // moe_out[b] = comb[b] @ ymoe[b] -> f32
    hgemm<<<dim3(8, 8, 4), T>>>(combh, ymoeh, nullptr, moeout, nullptr, 1024, 1024, 1024,
                                1048576, 1048576, 0, 1048576, 0, 0);

    // y = LN(moe_out + 2*x1)
    ln_res<<<4096, T>>>(moeout, x1, 2.0f, g2, b2, out, nullptr);
}

// round 14
// speedup vs baseline: 1.9736x; 1.0073x over previous
#include <cuda_runtime.h>
#include <cuda_fp16.h>
#include <math.h>
#include <stdint.h>

// ---------------------------------------------------------------------------
// Problem constants
//   B=4, SEQ=1024, DIM=1024, HEADS=16, N_EXP=2, SLOTS=512, HID=4096
// Output: [ y : 4*1024*1024 f32 ][ attn : 4*1024*1024*16 f32 ]
// All GEMM/attention operands fp16 (RNE-rounded at producer), fp32 accumulate.
// ---------------------------------------------------------------------------

// arena offsets in FLOAT units (fp16 buffers occupy elem_count/2 float slots)
#define OFF_TMP      0LL           // 64M halves = 32M floats
#define OFF_PROJ     33554432LL    // 4M f32
#define OFF_X1       37748736LL    // 4M f32
#define OFF_LOGITS   41943040LL    // 4M f32
#define OFF_MOE      46137344LL    // 4M f32
#define OFF_RL       50331648LL    // 64K f32
#define OFF_XH       50397184LL    // 4M halves
#define OFF_WQH      52494336LL    // 1M halves
#define OFF_WKVH     53018624LL    // 2M halves
#define OFF_WPH      54067200LL    // 1M halves
#define OFF_PHIH     54591488LL    // 1M halves
#define OFF_WE1H     55115776LL    // 8M halves
#define OFF_WE2H     59310080LL    // 8M halves
#define OFF_QH       63504384LL    // 4M halves
#define OFF_KVH      65601536LL    // 8M halves
#define OFF_ATTOUTH  69795840LL    // 4M halves
#define OFF_X1H      71892992LL    // 4M halves
#define OFF_DISPTH   73990144LL    // 4M halves
#define OFF_COMBH    76087296LL    // 4M halves
#define OFF_SLOTSH   78184448LL    // 4M halves (4 batches x 1024x1024)
#define OFF_HH       80281600LL    // 16M halves (8 batches x 512x4096)
#define OFF_YMOEH    88670208LL    // 4M halves (8 batches x 512x1024)
#define ARENA_FLOATS 90767360LL

__device__ float g_arena[ARENA_FLOATS];

__device__ __forceinline__ float gelu_tanh(float v) {
    const float c0 = 0.7978845608028654f;   // sqrt(2/pi)
    float t = tanhf(c0 * (v + 0.044715f * v * v * v));
    return 0.5f * v * (1.0f + t);
}

__device__ __forceinline__ uint32_t smem_u32(const void* p) {
    return (uint32_t)__cvta_generic_to_shared(p);
}

#define CP16(dst, src) \
    asm volatile("cp.async.cg.shared.global [%0], [%1], 16;" :: "r"(dst), "l"(src))
#define CP_COMMIT() asm volatile("cp.async.commit_group;")
#define CP_WAIT0()  asm volatile("cp.async.wait_group 0;")

#define MMA_F16(c0,c1,c2,c3,a0,a1,a2,a3,b0,b1)                                \
    asm volatile("mma.sync.aligned.m16n8k16.row.col.f32.f16.f16.f32 "         \
                 "{%0,%1,%2,%3},{%4,%5,%6,%7},{%8,%9},{%0,%1,%2,%3};"         \
                 : "+f"(c0), "+f"(c1), "+f"(c2), "+f"(c3)                     \
                 : "r"(a0), "r"(a1), "r"(a2), "r"(a3), "r"(b0), "r"(b1))

#define LDSM_X4(r0,r1,r2,r3,addr)                                             \
    asm volatile("ldmatrix.sync.aligned.m8n8.x4.shared.b16 {%0,%1,%2,%3}, [%4];" \
                 : "=r"(r0), "=r"(r1), "=r"(r2), "=r"(r3) : "r"(addr))

#define LDSM_X4_T(r0,r1,r2,r3,addr)                                           \
    asm volatile("ldmatrix.sync.aligned.m8n8.x4.trans.shared.b16 {%0,%1,%2,%3}, [%4];" \
                 : "=r"(r0), "=r"(r1), "=r"(r2), "=r"(r3) : "r"(addr))

// ---------------------------------------------------------------------------
// RNE-round all seven GEMM input buffers f32 -> fp16 in ONE launch.
// ---------------------------------------------------------------------------
__global__ void round_all(const float* __restrict__ x,  const float* __restrict__ Wq,
                          const float* __restrict__ Wkv,const float* __restrict__ Wp,
                          const float* __restrict__ phi,const float* __restrict__ We1,
                          const float* __restrict__ We2,
                          __half* __restrict__ xh,  __half* __restrict__ Wqh,
                          __half* __restrict__ Wkvh,__half* __restrict__ Wph,
                          __half* __restrict__ phih,__half* __restrict__ We1h,
                          __half* __restrict__ We2h)
{
    long long i = (long long)blockIdx.x * blockDim.x + threadIdx.x;
    const float* s; __half* d; long long off;
    if      (i < 1048576LL) { s = x;   d = xh;   off = i; }
    else if (i < 1310720LL) { s = Wq;  d = Wqh;  off = i - 1048576LL; }
    else if (i < 1835008LL) { s = Wkv; d = Wkvh; off = i - 1310720LL; }
    else if (i < 2097152LL) { s = Wp;  d = Wph;  off = i - 1835008LL; }
    else if (i < 2359296LL) { s = phi; d = phih; off = i - 2097152LL; }
    else if (i < 4456448LL) { s = We1; d = We1h; off = i - 2359296LL; }
    else if (i < 6553600LL) { s = We2; d = We2h; off = i - 4456448LL; }
    else return;
    float4 v = ((const float4*)s)[off];
    __half2 h01 = __floats2half2_rn(v.x, v.y);
    __half2 h23 = __floats2half2_rn(v.z, v.w);
    uint2 o;
    o.x = *(uint32_t*)&h01;
    o.y = *(uint32_t*)&h23;
    ((uint2*)d)[off] = o;
}

// ---------------------------------------------------------------------------
// fp16 tensor-core batched GEMM (m16n8k16, fp32 accum). (R12 version)
// ---------------------------------------------------------------------------
__global__ void __launch_bounds__(256, 2)
hgemm(const __half* __restrict__ A, const __half* __restrict__ Bm,
      const float* __restrict__ bias, float* __restrict__ Cf,
      __half* __restrict__ Ch,
      int M, int N, int K,
      long long sA, long long sB, long long sBias, long long sC,
      int nBmod, int act)
{
    int z = blockIdx.z;
    int zb = nBmod ? (z % nBmod) : z;
    A  += (long long)z * sA;
    Bm += (long long)zb * sB;
    if (act >= 1) bias += (long long)zb * sBias;
    if (Cf) Cf += (long long)z * sC;
    if (Ch) Ch += (long long)z * sC;

    __shared__ __half As[2][128][40];   // [m][k32 pad 40]
    __shared__ __half Bs[2][32][136];   // [k][n128 pad 136]

    int bx = blockIdx.x, by = blockIdx.y;
    int tid = threadIdx.x;
    int wid = tid >> 5;
    int lane = tid & 31;
    int g = lane >> 2;
    int j = lane & 3;
    int wm64 = (wid >> 2) * 64;
    int wn32 = (wid & 3) * 32;

    int aRow = tid >> 1;
    int aKc  = (tid & 1) * 16;
    int bRow = tid >> 3;
    int bCc  = (tid & 7) * 16;

    const __half* Ap = A + (long long)(by * 128 + aRow) * K + aKc;
    const __half* Bp = Bm + (long long)bRow * N + bx * 128 + bCc;

    uint32_t aSm = smem_u32(&As[0][aRow][aKc]);
    uint32_t bSm = smem_u32(&Bs[0][bRow][bCc]);
    const uint32_t A_BUF = 128 * 40 * 2;
    const uint32_t B_BUF = 32 * 136 * 2;

    int lmat = lane >> 3, lrow = lane & 7;
    uint32_t aFrag[4];
    #pragma unroll
    for (int mt = 0; mt < 4; mt++)
        aFrag[mt] = smem_u32(
            &As[0][wm64 + mt * 16 + (lmat & 1) * 8 + lrow][(lmat >> 1) * 8]);
    uint32_t bFrag[2];
    #pragma unroll
    for (int p = 0; p < 2; p++)
        bFrag[p] = smem_u32(
            &Bs[0][(lmat & 1) * 8 + lrow][wn32 + p * 16 + (lmat >> 1) * 8]);

    float c[4][4][4];
    #pragma unroll
    for (int mt = 0; mt < 4; mt++)
        #pragma unroll
        for (int nt = 0; nt < 4; nt++)
            #pragma unroll
            for (int r = 0; r < 4; r++) c[mt][nt][r] = 0.0f;

    CP16(aSm, Ap);            CP16(aSm + 16, Ap + 8);
    CP16(bSm, Bp);            CP16(bSm + 16, Bp + 8);
    CP_COMMIT();

    int buf = 0;
    for (int k0 = 0; k0 < K; k0 += 32) {
        CP_WAIT0();
        __syncthreads();

        if (k0 + 32 < K) {
            Ap += 32;
            Bp += (long long)32 * N;
            uint32_t aD = aSm + (buf ^ 1) * A_BUF;
            uint32_t bD = bSm + (buf ^ 1) * B_BUF;
            CP16(aD, Ap);        CP16(aD + 16, Ap + 8);
            CP16(bD, Bp);        CP16(bD + 16, Bp + 8);
            CP_COMMIT();
        }

        uint32_t aB = (uint32_t)buf * A_BUF;
        uint32_t bB = (uint32_t)buf * B_BUF;

        #pragma unroll
        for (int kk = 0; kk < 32; kk += 16) {
            uint32_t a[4][4];
            uint32_t bfr[4][2];
            #pragma unroll
            for (int mt = 0; mt < 4; mt++)
                LDSM_X4(a[mt][0], a[mt][1], a[mt][2], a[mt][3],
                        aFrag[mt] + aB + kk * 2);
            #pragma unroll
            for (int p = 0; p < 2; p++)
                LDSM_X4_T(bfr[2 * p][0], bfr[2 * p][1],
                          bfr[2 * p + 1][0], bfr[2 * p + 1][1],
                          bFrag[p] + bB + kk * 272);
            #pragma unroll
            for (int mt = 0; mt < 4; mt++)
                #pragma unroll
                for (int nt = 0; nt < 4; nt++)
                    MMA_F16(c[mt][nt][0], c[mt][nt][1], c[mt][nt][2], c[mt][nt][3],
                            a[mt][0], a[mt][1], a[mt][2], a[mt][3],
                            bfr[nt][0], bfr[nt][1]);
        }
        buf ^= 1;
    }

    #pragma unroll
    for (int mt = 0; mt < 4; mt++) {
        int r0 = by * 128 + wm64 + mt * 16 + g;
        #pragma unroll
        for (int nt = 0; nt < 4; nt++) {
            int col = bx * 128 + wn32 + nt * 8 + 2 * j;
            float b0 = 0.0f, b1 = 0.0f;
            if (act >= 1) { b0 = bias[col]; b1 = bias[col + 1]; }
            float v0 = c[mt][nt][0] + b0;
            float v1 = c[mt][nt][1] + b1;
            float v2 = c[mt][nt][2] + b0;
            float v3 = c[mt][nt][3] + b1;
            if (act == 2) {
                v0 = gelu_tanh(v0); v1 = gelu_tanh(v1);
                v2 = gelu_tanh(v2); v3 = gelu_tanh(v3);
            }
            if (Cf) {
                *(float2*)(Cf + (long long)r0 * N + col)       = make_float2(v0, v1);
                *(float2*)(Cf + (long long)(r0 + 8) * N + col) = make_float2(v2, v3);
            }
            if (Ch) {
                __half2 h01 = __floats2half2_rn(v0, v1);
                __half2 h23 = __floats2half2_rn(v2, v3);
                *(uint32_t*)(Ch + (long long)r0 * N + col)       = *(uint32_t*)&h01;
                *(uint32_t*)(Ch + (long long)(r0 + 8) * N + col) = *(uint32_t*)&h23;
            }
        }
    }
}

// ---------------------------------------------------------------------------
// Fused attention (fp16 HMMA): per (b,h), n-tile 64.  (R12 version: static
// smem pad-72 rows, occ ~42%.)
// S = Q K^T; E = exp(0.125*S) -> fp16 (tmp + smem Ps); O = (E@V)/rowsum.
// ---------------------------------------------------------------------------
__global__ void __launch_bounds__(256)
att_fused(const __half* __restrict__ qh, const __half* __restrict__ kvh,
          __half* __restrict__ tmp, float* __restrict__ rowrl,
          __half* __restrict__ attouth)
{
    int bh = blockIdx.y;
    int b = bh >> 4, h = bh & 15;
    int n0 = blockIdx.x * 64;

    __shared__ __half Qs[64][72];   // [n][d]
    __shared__ __half Kt[64][72];   // [m][d]
    __shared__ __half Vs[64][72];   // [m][d]
    __shared__ __half Ps[64][72];   // [n][m-chunk]
    __shared__ float sums[4][64];

    int tid = threadIdx.x, lane = tid & 31, wid = tid >> 5;
    int g = lane >> 2, j = lane & 3;
    int wm32 = (wid >> 2) * 32;
    int wn16 = (wid & 3) * 16;

    sums[tid >> 6][tid & 63] = 0.0f;

    for (int i = tid; i < 512; i += 256) {
        int r = i >> 3, seg = (i & 7) * 8;
        *(uint4*)&Qs[r][seg] =
            *(const uint4*)(qh + ((size_t)(b * 1024 + n0 + r) * 1024) + h * 64 + seg);
    }

    int lmat = lane >> 3, lrow = lane & 7;
    uint32_t vFrag = smem_u32(&Vs[(lmat & 1) * 8 + lrow][wn16 + (lmat >> 1) * 8]);

    float o[2][2][4];
    #pragma unroll
    for (int mt = 0; mt < 2; mt++)
        #pragma unroll
        for (int nt = 0; nt < 2; nt++)
            #pragma unroll
            for (int r = 0; r < 4; r++) o[mt][nt][r] = 0.0f;

    for (int m0 = 0; m0 < 1024; m0 += 64) {
        __syncthreads();
        for (int i = tid; i < 512; i += 256) {
            int r = i >> 3, seg = (i & 7) * 8;
            const __half* kb = kvh + ((size_t)(b * 1024 + m0 + r) * 2048) + h * 64 + seg;
            *(uint4*)&Kt[r][seg] = *(const uint4*)kb;
            *(uint4*)&Vs[r][seg] = *(const uint4*)(kb + 1024);
        }
        __syncthreads();

        // S-mma
        float c[2][2][4];
        #pragma unroll
        for (int mt = 0; mt < 2; mt++)
            #pragma unroll
            for (int nt = 0; nt < 2; nt++)
                #pragma unroll
                for (int r = 0; r < 4; r++) c[mt][nt][r] = 0.0f;

        #pragma unroll
        for (int kk = 0; kk < 64; kk += 16) {
            uint32_t a[2][4], bf[2][2];
            #pragma unroll
            for (int mt = 0; mt < 2; mt++) {
                const __half* p0 = &Qs[wm32 + mt * 16 + g][kk + 2 * j];
                a[mt][0] = *(const uint32_t*)p0;
                a[mt][1] = *(const uint32_t*)(p0 + 8 * 72);
                a[mt][2] = *(const uint32_t*)(p0 + 8);
                a[mt][3] = *(const uint32_t*)(p0 + 8 * 72 + 8);
            }
            #pragma unroll
            for (int nt = 0; nt < 2; nt++) {
                const __half* p0 = &Kt[wn16 + nt * 8 + g][kk + 2 * j];
                bf[nt][0] = *(const uint32_t*)p0;
                bf[nt][1] = *(const uint32_t*)(p0 + 8);
            }
            #pragma unroll
            for (int mt = 0; mt < 2; mt++)
                #pragma unroll
                for (int nt = 0; nt < 2; nt++)
                    MMA_F16(c[mt][nt][0], c[mt][nt][1], c[mt][nt][2], c[mt][nt][3],
                            a[mt][0], a[mt][1], a[mt][2], a[mt][3],
                            bf[nt][0], bf[nt][1]);
        }

        // E = exp(0.125*S) -> fp16 (tmp, Ps); row sums of the fp16 values
        #pragma unroll
        for (int mt = 0; mt < 2; mt++) {
            int r1 = wm32 + mt * 16 + g;
            float eA = 0.0f, eB = 0.0f;
            #pragma unroll
            for (int nt = 0; nt < 2; nt++) {
                int col = wn16 + nt * 8 + 2 * j;
                float e0 = __expf(0.125f * c[mt][nt][0]);
                float e1 = __expf(0.125f * c[mt][nt][1]);
                float e2 = __expf(0.125f * c[mt][nt][2]);
                float e3 = __expf(0.125f * c[mt][nt][3]);
                __half2 h01 = __floats2half2_rn(e0, e1);
                __half2 h23 = __floats2half2_rn(e2, e3);
                size_t idx = ((size_t)bh * 1024 + n0 + r1) * 1024 + m0 + col;
                __stcs((unsigned int*)(tmp + idx),            *(uint32_t*)&h01);
                __stcs((unsigned int*)(tmp + idx + 8 * 1024), *(uint32_t*)&h23);
                *(uint32_t*)&Ps[r1][col]     = *(uint32_t*)&h01;
                *(uint32_t*)&Ps[r1 + 8][col] = *(uint32_t*)&h23;
                float2 f01 = __half22float2(h01);
                float2 f23 = __half22float2(h23);
                eA += f01.x + f01.y;
                eB += f23.x + f23.y;
            }
            eA += __shfl_xor_sync(0xffffffffu, eA, 1);
            eA += __shfl_xor_sync(0xffffffffu, eA, 2);
            eB += __shfl_xor_sync(0xffffffffu, eB, 1);
            eB += __shfl_xor_sync(0xffffffffu, eB, 2);
            if (j == 0) {
                sums[wn16 >> 4][r1]     += eA;
                sums[wn16 >> 4][r1 + 8] += eB;
            }
        }
        __syncthreads();

        // PV-mma: A = Ps (LDS.32 pairs), B = Vs (ldmatrix.trans)
        #pragma unroll
        for (int kk = 0; kk < 64; kk += 16) {
            uint32_t a[2][4], bf[2][2];
            #pragma unroll
            for (int mt = 0; mt < 2; mt++) {
                const __half* p0 = &Ps[wm32 + mt * 16 + g][kk + 2 * j];
                a[mt][0] = *(const uint32_t*)p0;
                a[mt][1] = *(const uint32_t*)(p0 + 8 * 72);
                a[mt][2] = *(const uint32_t*)(p0 + 8);
                a[mt][3] = *(const uint32_t*)(p0 + 8 * 72 + 8);
            }
            LDSM_X4_T(bf[0][0], bf[0][1], bf[1][0], bf[1][1],
                      vFrag + kk * 144);
            #pragma unroll
            for (int mt = 0; mt < 2; mt++)
                #pragma unroll
                for (int nt = 0; nt < 2; nt++)
                    MMA_F16(o[mt][nt][0], o[mt][nt][1], o[mt][nt][2], o[mt][nt][3],
                            a[mt][0], a[mt][1], a[mt][2], a[mt][3],
                            bf[nt][0], bf[nt][1]);
        }
    }

    __syncthreads();
    if (tid < 64) {
        float tot = sums[0][tid] + sums[1][tid] + sums[2][tid] + sums[3][tid];
        float r = 1.0f / tot;
        sums[0][tid] = r;
        rowrl[(size_t)bh * 1024 + n0 + tid] = r;
    }
    __syncthreads();

    #pragma unroll
    for (int mt = 0; mt < 2; mt++) {
        int r1 = wm32 + mt * 16 + g;
        float rlA = sums[0][r1], rlB = sums[0][r1 + 8];
        #pragma unroll
        for (int nt = 0; nt < 2; nt++) {
            int col = wn16 + nt * 8 + 2 * j;
            __half* base = attouth + ((size_t)(b * 1024 + n0 + r1) * 1024) + h * 64 + col;
            __half2 h01 = __floats2half2_rn(o[mt][nt][0] * rlA, o[mt][nt][1] * rlA);
            __half2 h23 = __floats2half2_rn(o[mt][nt][2] * rlB, o[mt][nt][3] * rlB);
            *(uint32_t*)base              = *(uint32_t*)&h01;
            *(uint32_t*)(base + 8 * 1024) = *(uint32_t*)&h23;
        }
    }
}

// ---------------------------------------------------------------------------
// Normalize + transpose: out(b,n,m,h) = E_fp16(b,h,n,m) * rl(b,h,n).
// Block per (b,n); 4 m-chunks of 256. uint4 loads for MLP depth.
// ---------------------------------------------------------------------------
__global__ void attn_tr(const __half* __restrict__ tmp, const float* __restrict__ rowrl,
                        float* __restrict__ outAttn)
{
    int b = blockIdx.y;
    int n = blockIdx.x;
    __shared__ float T[16][257];
    __shared__ float rl_s[16];
    int tid = threadIdx.x;
    if (tid < 16) rl_s[tid] = rowrl[(size_t)(b * 16 + tid) * 1024 + n];
    __syncthreads();

    for (int m0 = 0; m0 < 1024; m0 += 256) {
        for (int i = tid; i < 512; i += 256) {
            int hh = i & 15;
            int mm = (i >> 4) * 8;
            uint4 raw = __ldcs((const uint4*)
                (tmp + ((size_t)(b * 16 + hh) * 1024 + n) * 1024 + m0 + mm));
            float rl = rl_s[hh];
            __half2 v0 = *(__half2*)&raw.x;
            __half2 v1 = *(__half2*)&raw.y;
            __half2 v2 = *(__half2*)&raw.z;
            __half2 v3 = *(__half2*)&raw.w;
            float2 f0 = __half22float2(v0);
            float2 f1 = __half22float2(v1);
            float2 f2 = __half22float2(v2);
            float2 f3 = __half22float2(v3);
            float* tr = &T[hh][mm];
            tr[0] = f0.x * rl; tr[1] = f0.y * rl;
            tr[2] = f1.x * rl; tr[3] = f1.y * rl;
            tr[4] = f2.x * rl; tr[5] = f2.y * rl;
            tr[6] = f3.x * rl; tr[7] = f3.y * rl;
        }
        __syncthreads();
        float* dst = outAttn + ((size_t)(b * 1024 + n) * 1024 + m0 + tid) * 16;
        #pragma unroll
        for (int k = 0; k < 16; k += 4) {
            __stcs((float4*)(dst + k),
                   make_float4(T[k][tid], T[k + 1][tid], T[k + 2][tid], T[k + 3][tid]));
        }
        __syncthreads();
    }
}

// ---------------------------------------------------------------------------
// Row softmax over contiguous 1024 (combine weights), fp16 out.
// ---------------------------------------------------------------------------
__global__ void row_softmax(const float* __restrict__ in, __half* __restrict__ outp)
{
    size_t row = blockIdx.x;
    const float4* L = (const float4*)(in + row * 1024);
    int t = threadIdx.x;
    float4 v = L[t];
    float mx = fmaxf(fmaxf(v.x, v.y), fmaxf(v.z, v.w));
    __shared__ float smA[8], smB[8];
    #pragma unroll
    for (int off = 16; off; off >>= 1) mx = fmaxf(mx, __shfl_xor_sync(0xffffffffu, mx, off));
    if ((t & 31) == 0) smA[t >> 5] = mx;
    __syncthreads();
    mx = smA[0];
    #pragma unroll
    for (int w = 1; w < 8; w++) mx = fmaxf(mx, smA[w]);
    float e0 = __expf(v.x - mx), e1 = __expf(v.y - mx);
    float e2 = __expf(v.z - mx), e3 = __expf(v.w - mx);
    float s = e0 + e1 + e2 + e3;
    #pragma unroll
    for (int off = 16; off; off >>= 1) s += __shfl_xor_sync(0xffffffffu, s, off);
    if ((t & 31) == 0) smB[t >> 5] = s;
    __syncthreads();
    s = 0.0f;
    #pragma unroll
    for (int w = 0; w < 8; w++) s += smB[w];
    float r = 1.0f / s;
    __half2 h01 = __floats2half2_rn(e0 * r, e1 * r);
    __half2 h23 = __floats2half2_rn(e2 * r, e3 * r);
    uint2 o;
    o.x = *(uint32_t*)&h01;
    o.y = *(uint32_t*)&h23;
    ((uint2*)(outp + row * 1024))[t] = o;
}

// ---------------------------------------------------------------------------
// Dispatch softmax over token axis n, written TRANSPOSED, fp16 out.
// ---------------------------------------------------------------------------
__global__ void disp_softmax(const float* __restrict__ logits, __half* __restrict__ dispT)
{
    int b = blockIdx.y;
    int c0 = blockIdx.x * 64;
    const float* L = logits + (size_t)b * 1048576;
    __half* O = dispT + (size_t)b * 1048576;
    int tid = threadIdx.x;
    int tx = tid & 63, ty = tid >> 6;   // 4 x 64
    int col = c0 + tx;

    __shared__ float red[4][64];
    float mx = -1e30f;
    for (int n = ty; n < 1024; n += 4) mx = fmaxf(mx, L[(size_t)n * 1024 + col]);
    red[ty][tx] = mx;
    __syncthreads();
    mx = fmaxf(fmaxf(red[0][tx], red[1][tx]), fmaxf(red[2][tx], red[3][tx]));
    __syncthreads();
    float s = 0.0f;
    for (int n = ty; n < 1024; n += 4) s += __expf(L[(size_t)n * 1024 + col] - mx);
    red[ty][tx] = s;
    __syncthreads();
    s = red[0][tx] + red[1][tx] + red[2][tx] + red[3][tx];
    float rinv = 1.0f / s;
    __syncthreads();

    __shared__ float T[64][65];
    for (int n0 = 0; n0 < 1024; n0 += 64) {
        for (int n = ty; n < 64; n += 4)
            T[tx][n] = __expf(L[(size_t)(n0 + n) * 1024 + col] - mx) * rinv;
        __syncthreads();
        int cl = tid >> 2;
        int nl = (tid & 3) * 16;
        __half* dst = O + (size_t)(c0 + cl) * 1024 + n0 + nl;
        #pragma unroll
        for (int k = 0; k < 16; k += 4) {
            __half2 h01 = __floats2half2_rn(T[cl][nl + k],     T[cl][nl + k + 1]);
            __half2 h23 = __floats2half2_rn(T[cl][nl + k + 2], T[cl][nl + k + 3]);
            uint2 o;
            o.x = *(uint32_t*)&h01;
            o.y = *(uint32_t*)&h23;
            *(uint2*)(dst + k) = o;
        }
        __syncthreads();
    }
}

// ---------------------------------------------------------------------------
// Fused residual + LayerNorm: out = LN(a + coefb * bsrc) * g + beta.
// If outH != null: values RNE-rounded to fp16, written to BOTH outputs.
// ---------------------------------------------------------------------------
__global__ void ln_res(const float* __restrict__ a, const float* __restrict__ bsrc,
                       float coefb, const float* __restrict__ g,
                       const float* __restrict__ beta, float* __restrict__ outp,
                       __half* __restrict__ outH)
{
    size_t row = blockIdx.x;
    int t = threadIdx.x;
    float4 av = ((const float4*)(a + row * 1024))[t];
    float4 bv = ((const float4*)(bsrc + row * 1024))[t];
    float x0 = av.x + coefb * bv.x;
    float x1 = av.y + coefb * bv.y;
    float x2 = av.z + coefb * bv.z;
    float x3 = av.w + coefb * bv.w;
    float s = x0 + x1 + x2 + x3;
    float q = x0 * x0 + x1 * x1 + x2 * x2 + x3 * x3;
    __shared__ float smA[8], smB[8];
    #pragma unroll
    for (int off = 16; off; off >>= 1) {
        s += __shfl_xor_sync(0xffffffffu, s, off);
        q += __shfl_xor_sync(0xffffffffu, q, off);
    }
    if ((t & 31) == 0) { smA[t >> 5] = s; smB[t >> 5] = q; }
    __syncthreads();
    s = 0.0f; q = 0.0f;
    #pragma unroll
    for (int w = 0; w < 8; w++) { s += smA[w]; q += smB[w]; }
    float mu = s * (1.0f / 1024.0f);
    float var = q * (1.0f / 1024.0f) - mu * mu;
    float rs = rsqrtf(var + 1e-5f);
    float4 gv = ((const float4*)g)[t];
    float4 btv = ((const float4*)beta)[t];
    float4 out4;
    out4.x = (x0 - mu) * rs * gv.x + btv.x;
    out4.y = (x1 - mu) * rs * gv.y + btv.y;
    out4.z = (x2 - mu) * rs * gv.z + btv.z;
    out4.w = (x3 - mu) * rs * gv.w + btv.w;
    if (outH) {
        __half2 h01 = __floats2half2_rn(out4.x, out4.y);
        __half2 h23 = __floats2half2_rn(out4.z, out4.w);
        uint2 o;
        o.x = *(uint32_t*)&h01;
        o.y = *(uint32_t*)&h23;
        ((uint2*)(outH + row * 1024))[t] = o;
        float2 f01 = __half22float2(h01);
        float2 f23 = __half22float2(h23);
        out4.x = f01.x; out4.y = f01.y; out4.z = f23.x; out4.w = f23.y;
    }
    ((float4*)(outp + row * 1024))[t] = out4;
}

// ---------------------------------------------------------------------------
// Launcher. attn_tr runs on a side stream, overlapping the proj->LN->MoE
// chain (it has no downstream consumers; joined before the final LN).
// Stream/events created once; identical launch-work on every call.
// ---------------------------------------------------------------------------
static cudaStream_t g_side = nullptr;
static cudaEvent_t  g_evA  = nullptr;
static cudaEvent_t  g_evB  = nullptr;

extern "C" void kernel_launch(void* const* d_in, const int* in_sizes, int n_in,
                              void* d_out, int out_size)
{
    const float* x   = (const float*)d_in[0];
    const float* Wq  = (const float*)d_in[1];
    const float* bq  = (const float*)d_in[2];
    const float* Wkv = (const float*)d_in[3];
    const float* bkv = (const float*)d_in[4];
    const float* Wp  = (const float*)d_in[5];
    const float* bp  = (const float*)d_in[6];
    const float* g1  = (const float*)d_in[7];
    const float* b1  = (const float*)d_in[8];
    const float* phi = (const float*)d_in[9];
    const float* We1 = (const float*)d_in[10];
    const float* be1 = (const float*)d_in[11];
    const float* We2 = (const float*)d_in[12];
    const float* be2 = (const float*)d_in[13];
    const float* g2  = (const float*)d_in[14];
    const float* b2  = (const float*)d_in[15];

    if (!g_side) {
        cudaStreamCreateWithFlags(&g_side, cudaStreamNonBlocking);
        cudaEventCreateWithFlags(&g_evA, cudaEventDisableTiming);
        cudaEventCreateWithFlags(&g_evB, cudaEventDisableTiming);
    }

    float* arena = nullptr;
    cudaGetSymbolAddress((void**)&arena, g_arena);

    __half* tmp     = (__half*)(arena + OFF_TMP);
    float*  proj    = arena + OFF_PROJ;
    float*  x1      = arena + OFF_X1;
    float*  logits  = arena + OFF_LOGITS;
    float*  moeout  = arena + OFF_MOE;
    float*  rl      = arena + OFF_RL;
    __half* xh      = (__half*)(arena + OFF_XH);
    __half* Wqh     = (__half*)(arena + OFF_WQH);
    __half* Wkvh    = (__half*)(arena + OFF_WKVH);
    __half* Wph     = (__half*)(arena + OFF_WPH);
    __half* phih    = (__half*)(arena + OFF_PHIH);
    __half* We1h    = (__half*)(arena + OFF_WE1H);
    __half* We2h    = (__half*)(arena + OFF_WE2H);
    __half* qh      = (__half*)(arena + OFF_QH);
    __half* kvh     = (__half*)(arena + OFF_KVH);
    __half* attouth = (__half*)(arena + OFF_ATTOUTH);
    __half* x1h     = (__half*)(arena + OFF_X1H);
    __half* dispTh  = (__half*)(arena + OFF_DISPTH);
    __half* combh   = (__half*)(arena + OFF_COMBH);
    __half* slotsh  = (__half*)(arena + OFF_SLOTSH);
    __half* hh      = (__half*)(arena + OFF_HH);
    __half* ymoeh   = (__half*)(arena + OFF_YMOEH);

    float* out = (float*)d_out;
    float* outAttn = out + 4194304;

    dim3 T(256);

    // prep: RNE-round all GEMM inputs to fp16, one launch
    round_all<<<25600, T>>>(x, Wq, Wkv, Wp, phi, We1, We2,
                            xh, Wqh, Wkvh, Wph, phih, We1h, We2h);

    // q = x @ Wq + bq          (4096x1024x1024) -> fp16
    hgemm<<<dim3(8, 32, 1), T>>>(xh, Wqh, bq, nullptr, qh, 4096, 1024, 1024,
                                 0, 0, 0, 0, 1, 1);
    // kv = x @ Wkv + bkv       (4096x2048x1024) -> fp16
    hgemm<<<dim3(16, 32, 1), T>>>(xh, Wkvh, bkv, nullptr, kvh, 4096, 2048, 1024,
                                  0, 0, 0, 0, 1, 1);

    // fused attention
    att_fused<<<dim3(16, 64), T>>>(qh, kvh, tmp, rl, attouth);

    // fork: attn_tr on side stream (depends only on att_fused outputs)
    cudaEventRecord(g_evA, 0);
    cudaStreamWaitEvent(g_side, g_evA, 0);
    attn_tr<<<dim3(1024, 4), T, 0, g_side>>>(tmp, rl, outAttn);
    cudaEventRecord(g_evB, g_side);

    // out-proj (f32) + residual LN (x1 f32 + fp16)   [main stream]
    hgemm<<<dim3(8, 32, 1), T>>>(attouth, Wph, bp, proj, nullptr, 4096, 1024, 1024,
                                 0, 0, 0, 0, 1, 1);
    ln_res<<<4096, T>>>(proj, x, 1.0f, g1, b1, x1, x1h);

    // soft-MoE
    hgemm<<<dim3(8, 32, 1), T>>>(x1h, phih, nullptr, logits, nullptr, 4096, 1024, 1024,
                                 0, 0, 0, 0, 1, 0);
    row_softmax<<<4096, T>>>(logits, combh);
    disp_softmax<<<dim3(16, 4), T>>>(logits, dispTh);

    // slots[b] = dispT[b] @ x1[b] -> fp16
    hgemm<<<dim3(8, 8, 4), T>>>(dispTh, x1h, nullptr, nullptr, slotsh, 1024, 1024, 1024,
                                1048576, 1048576, 0, 1048576, 0, 0);
    // h = gelu(slots @ We1[e] + be1[e]) -> fp16
    hgemm<<<dim3(32, 4, 8), T>>>(slotsh, We1h, be1, nullptr, hh, 512, 4096, 1024,
                                 524288, 4194304, 4096, 2097152, 2, 2);
    // y = h @ We2[e] + be2[e] -> fp16
    hgemm<<<dim3(8, 4, 8), T>>>(hh, We2h, be2, nullptr, ymoeh, 512, 1024, 4096,
                                2097152, 4194304, 1024, 524288, 2, 1);
    // moe_out[b] = comb[b] @ ymoe[b] -> f32
    hgemm<<<dim3(8, 8, 4), T>>>(combh, ymoeh, nullptr, moeout, nullptr, 1024, 1024, 1024,
                                1048576, 1048576, 0, 1048576, 0, 0);

    // join side stream, then final LN
    cudaStreamWaitEvent(0, g_evB, 0);
    ln_res<<<4096, T>>>(moeout, x1, 2.0f, g2, b2, out, nullptr);
}